// round 3
// baseline (speedup 1.0000x reference)
#include <cuda_runtime.h>
#include <stdint.h>
#include <math.h>

#define HEADS 12
#define HD 64
#define DIMC 768
#define NB 4
#define NN 1024
#define LDQKV (3 * DIMC)
#define ATT_SCALE 0.125f

// ---------------- scratch ----------------
__device__ float g_qkv[(size_t)NB * NN * 3 * DIMC];
__device__ float g_S[(size_t)NB * HEADS * NN * NN];
__device__ float g_Av[(size_t)NB * HEADS * NN * HD];
__device__ float g_O[(size_t)NB * NN * DIMC];

// ---------------- tf32 helpers ----------------
__device__ __forceinline__ uint32_t f2tf(float x) {
    uint32_t u; asm("cvt.rna.tf32.f32 %0, %1;" : "=r"(u) : "f"(x)); return u;
}
__device__ __forceinline__ void split_tf32(float x, uint32_t &hi, uint32_t &lo) {
    hi = f2tf(x);
    lo = f2tf(x - __uint_as_float(hi));
}
__device__ __forceinline__ void mma_tf32(float *c, const uint32_t *a, const uint32_t *b) {
    asm volatile(
        "mma.sync.aligned.m16n8k8.row.col.f32.tf32.tf32.f32 "
        "{%0,%1,%2,%3}, {%4,%5,%6,%7}, {%8,%9}, {%0,%1,%2,%3};"
        : "+f"(c[0]), "+f"(c[1]), "+f"(c[2]), "+f"(c[3])
        : "r"(a[0]), "r"(a[1]), "r"(a[2]), "r"(a[3]), "r"(b[0]), "r"(b[1]));
}

// Fragment-packed smem addressing (m16n8k8):
//  A element (m within 16-row frag: r, k within 8: kk):
//    lane = (r&7)*4 + (kk&3), reg = (r>>3) + 2*(kk>>2)
//  B element (k within 8: kk, n within 8-col frag: c):
//    lane = c*4 + (kk&3),     reg = (kk>>2)

// ---------------- NT tile: C[M,N] = alpha * A[M,K] @ B[N,K]^T (+bias) ----------------
// BM=128, BN=128, BK=16, 256 threads (8 warps, 2x4 grid, warp tile 64x32). tf32x3.
__device__ __forceinline__ void mma_nt_128x128(
    const float* __restrict__ A, int lda,
    const float* __restrict__ B, int ldb,
    float* __restrict__ C, int ldc,
    int K, float alpha, const float* __restrict__ bias)
{
    __shared__ __align__(16) uint32_t Ah[2 * 8 * 32 * 4], Al[2 * 8 * 32 * 4];
    __shared__ __align__(16) uint32_t Bh[2 * 16 * 32 * 2], Bl[2 * 16 * 32 * 2];

    const int tid = threadIdx.x;
    const int lane = tid & 31, wid = tid >> 5;
    const int wm = wid >> 2, wn = wid & 3;
    const int g = lane >> 2, tig = lane & 3;
    const int row0 = blockIdx.y * 128, col0 = blockIdx.x * 128;

    float acc[4][4][4] = {};

    const int sm_ = tid >> 2;       // 0..63 (row within half-tile)
    const int skc = tid & 3;        // k-chunk (4 floats)
    const float* Aptr = A + (size_t)(row0 + sm_) * lda + skc * 4;
    const float* Bptr = B + (size_t)(col0 + sm_) * ldb + skc * 4;

    for (int k0 = 0; k0 < K; k0 += 16) {
        float4 va0 = *(const float4*)(Aptr + k0);
        float4 va1 = *(const float4*)(Aptr + (size_t)64 * lda + k0);
        float4 vb0 = *(const float4*)(Bptr + k0);
        float4 vb1 = *(const float4*)(Bptr + (size_t)64 * ldb + k0);
        __syncthreads();
        {
            const int k8 = skc >> 1, khi = skc & 1;
            const float fa0[4] = {va0.x, va0.y, va0.z, va0.w};
            const float fa1[4] = {va1.x, va1.y, va1.z, va1.w};
            const float fb0[4] = {vb0.x, vb0.y, vb0.z, vb0.w};
            const float fb1[4] = {vb1.x, vb1.y, vb1.z, vb1.w};
            {
                const int m = sm_;
                const int idx = ((k8 * 8 + (m >> 4)) * 32 + (m & 7) * 4) * 4 + ((m >> 3) & 1) + 2 * khi;
#pragma unroll
                for (int j = 0; j < 4; j++) { uint32_t h, l; split_tf32(fa0[j], h, l); Ah[idx + j * 4] = h; Al[idx + j * 4] = l; }
            }
            {
                const int m = sm_ + 64;
                const int idx = ((k8 * 8 + (m >> 4)) * 32 + (m & 7) * 4) * 4 + ((m >> 3) & 1) + 2 * khi;
#pragma unroll
                for (int j = 0; j < 4; j++) { uint32_t h, l; split_tf32(fa1[j], h, l); Ah[idx + j * 4] = h; Al[idx + j * 4] = l; }
            }
            {
                const int n = sm_;
                const int idx = ((k8 * 16 + (n >> 3)) * 32 + (n & 7) * 4) * 2 + khi;
#pragma unroll
                for (int j = 0; j < 4; j++) { uint32_t h, l; split_tf32(fb0[j], h, l); Bh[idx + j * 2] = h; Bl[idx + j * 2] = l; }
            }
            {
                const int n = sm_ + 64;
                const int idx = ((k8 * 16 + (n >> 3)) * 32 + (n & 7) * 4) * 2 + khi;
#pragma unroll
                for (int j = 0; j < 4; j++) { uint32_t h, l; split_tf32(fb1[j], h, l); Bh[idx + j * 2] = h; Bl[idx + j * 2] = l; }
            }
        }
        __syncthreads();
#pragma unroll
        for (int k8 = 0; k8 < 2; k8++) {
            uint32_t ah[4][4], al[4][4], bh[4][2], bl[4][2];
#pragma unroll
            for (int mf = 0; mf < 4; mf++) {
                const int off = ((k8 * 8 + wm * 4 + mf) * 32 + lane) * 4;
                uint4 th = *(const uint4*)&Ah[off];
                uint4 tl = *(const uint4*)&Al[off];
                ah[mf][0] = th.x; ah[mf][1] = th.y; ah[mf][2] = th.z; ah[mf][3] = th.w;
                al[mf][0] = tl.x; al[mf][1] = tl.y; al[mf][2] = tl.z; al[mf][3] = tl.w;
            }
#pragma unroll
            for (int nf = 0; nf < 4; nf++) {
                const int off = ((k8 * 16 + wn * 4 + nf) * 32 + lane) * 2;
                uint2 th = *(const uint2*)&Bh[off];
                uint2 tl = *(const uint2*)&Bl[off];
                bh[nf][0] = th.x; bh[nf][1] = th.y;
                bl[nf][0] = tl.x; bl[nf][1] = tl.y;
            }
#pragma unroll
            for (int mf = 0; mf < 4; mf++)
#pragma unroll
                for (int nf = 0; nf < 4; nf++) {
                    mma_tf32(acc[mf][nf], al[mf], bh[nf]);
                    mma_tf32(acc[mf][nf], ah[mf], bl[nf]);
                    mma_tf32(acc[mf][nf], ah[mf], bh[nf]);
                }
        }
    }

#pragma unroll
    for (int mf = 0; mf < 4; mf++) {
        const int row = row0 + wm * 64 + mf * 16 + g;
#pragma unroll
        for (int nf = 0; nf < 4; nf++) {
            const int col = col0 + wn * 32 + nf * 8 + tig * 2;
            const float b0 = bias ? bias[col] : 0.f;
            const float b1 = bias ? bias[col + 1] : 0.f;
            float2 lo = make_float2(fmaf(acc[mf][nf][0], alpha, b0), fmaf(acc[mf][nf][1], alpha, b1));
            float2 hi = make_float2(fmaf(acc[mf][nf][2], alpha, b0), fmaf(acc[mf][nf][3], alpha, b1));
            *(float2*)&C[(size_t)row * ldc + col] = lo;
            *(float2*)&C[(size_t)(row + 8) * ldc + col] = hi;
        }
    }
}

// ---------------- NN tile: 128x64, 4 warps (2x2), warp tile 64x32. tf32x3. ----------------
// MODE 0: C = A@B -> g_Av[z]. MODE 1: g_O = (1-2λ)Av + 3λ(A@B), B = Av.
template <int MODE>
__device__ __forceinline__ void mma_nn_128x64(
    const float* __restrict__ A, int lda,
    const float* __restrict__ B, int ldb,
    int z, int K, const float* __restrict__ lamb)
{
    __shared__ __align__(16) uint32_t Ah[2 * 8 * 32 * 4], Al[2 * 8 * 32 * 4];
    __shared__ __align__(16) uint32_t Bh[2 * 8 * 32 * 2], Bl[2 * 8 * 32 * 2];

    const int tid = threadIdx.x;
    const int lane = tid & 31, wid = tid >> 5;
    const int wm = wid >> 1, wn = wid & 1;
    const int g = lane >> 2, tig = lane & 3;
    const int row0 = blockIdx.y * 128;

    float acc[4][4][4] = {};

    const int am = tid >> 2, akc = tid & 3;            // A: 4 iters of 32 rows
    const int bkk = tid >> 4, bn0 = (tid & 15) * 4;    // B: 2 iters of 8 k-rows

    for (int k0 = 0; k0 < K; k0 += 16) {
        float4 va[4];
#pragma unroll
        for (int i = 0; i < 4; i++)
            va[i] = *(const float4*)(A + (size_t)(row0 + am + 32 * i) * lda + k0 + akc * 4);
        float4 vb[2];
#pragma unroll
        for (int i = 0; i < 2; i++)
            vb[i] = *(const float4*)(B + (size_t)(k0 + bkk + 8 * i) * ldb + bn0);
        __syncthreads();
        {
            const int k8 = akc >> 1, khi = akc & 1;
#pragma unroll
            for (int i = 0; i < 4; i++) {
                const int m = am + 32 * i;
                const int idx = ((k8 * 8 + (m >> 4)) * 32 + (m & 7) * 4) * 4 + ((m >> 3) & 1) + 2 * khi;
                const float f[4] = {va[i].x, va[i].y, va[i].z, va[i].w};
#pragma unroll
                for (int j = 0; j < 4; j++) { uint32_t h, l; split_tf32(f[j], h, l); Ah[idx + j * 4] = h; Al[idx + j * 4] = l; }
            }
#pragma unroll
            for (int i = 0; i < 2; i++) {
                const int kk = bkk + 8 * i;
                const int bk8 = kk >> 3, btig = kk & 3, bkhi = (kk >> 2) & 1;
                const int idx = ((bk8 * 8 + (bn0 >> 3)) * 32 + (bn0 & 7) * 4 + btig) * 2 + bkhi;
                const float f[4] = {vb[i].x, vb[i].y, vb[i].z, vb[i].w};
#pragma unroll
                for (int j = 0; j < 4; j++) { uint32_t h, l; split_tf32(f[j], h, l); Bh[idx + j * 8] = h; Bl[idx + j * 8] = l; }
            }
        }
        __syncthreads();
#pragma unroll
        for (int k8 = 0; k8 < 2; k8++) {
            uint32_t ah[4][4], al[4][4], bh[4][2], bl[4][2];
#pragma unroll
            for (int mf = 0; mf < 4; mf++) {
                const int off = ((k8 * 8 + wm * 4 + mf) * 32 + lane) * 4;
                uint4 th = *(const uint4*)&Ah[off];
                uint4 tl = *(const uint4*)&Al[off];
                ah[mf][0] = th.x; ah[mf][1] = th.y; ah[mf][2] = th.z; ah[mf][3] = th.w;
                al[mf][0] = tl.x; al[mf][1] = tl.y; al[mf][2] = tl.z; al[mf][3] = tl.w;
            }
#pragma unroll
            for (int nf = 0; nf < 4; nf++) {
                const int off = ((k8 * 8 + wn * 4 + nf) * 32 + lane) * 2;
                uint2 th = *(const uint2*)&Bh[off];
                uint2 tl = *(const uint2*)&Bl[off];
                bh[nf][0] = th.x; bh[nf][1] = th.y;
                bl[nf][0] = tl.x; bl[nf][1] = tl.y;
            }
#pragma unroll
            for (int mf = 0; mf < 4; mf++)
#pragma unroll
                for (int nf = 0; nf < 4; nf++) {
                    mma_tf32(acc[mf][nf], al[mf], bh[nf]);
                    mma_tf32(acc[mf][nf], ah[mf], bl[nf]);
                    mma_tf32(acc[mf][nf], ah[mf], bh[nf]);
                }
        }
    }

    if (MODE == 0) {
        float* Cp = g_Av + (size_t)z * NN * HD;
#pragma unroll
        for (int mf = 0; mf < 4; mf++) {
            const int row = row0 + wm * 64 + mf * 16 + g;
#pragma unroll
            for (int nf = 0; nf < 4; nf++) {
                const int col = wn * 32 + nf * 8 + tig * 2;
                *(float2*)&Cp[(size_t)row * HD + col]       = make_float2(acc[mf][nf][0], acc[mf][nf][1]);
                *(float2*)&Cp[(size_t)(row + 8) * HD + col] = make_float2(acc[mf][nf][2], acc[mf][nf][3]);
            }
        }
    } else {
        const int b = z / HEADS, h = z % HEADS;
        const float lam = lamb[h];
        const float c1 = 1.f - 2.f * lam, c3 = 3.f * lam;
        const float* Avp = g_Av + (size_t)z * NN * HD;
#pragma unroll
        for (int mf = 0; mf < 4; mf++) {
            const int row = row0 + wm * 64 + mf * 16 + g;
#pragma unroll
            for (int nf = 0; nf < 4; nf++) {
                const int col = wn * 32 + nf * 8 + tig * 2;
                float2 av0 = *(const float2*)&Avp[(size_t)row * HD + col];
                float2 av1 = *(const float2*)&Avp[(size_t)(row + 8) * HD + col];
                float* o0 = &g_O[((size_t)b * NN + row) * DIMC + h * HD + col];
                float* o1 = &g_O[((size_t)b * NN + row + 8) * DIMC + h * HD + col];
                *(float2*)o0 = make_float2(fmaf(c3, acc[mf][nf][0], c1 * av0.x),
                                           fmaf(c3, acc[mf][nf][1], c1 * av0.y));
                *(float2*)o1 = make_float2(fmaf(c3, acc[mf][nf][2], c1 * av1.x),
                                           fmaf(c3, acc[mf][nf][3], c1 * av1.y));
            }
        }
    }
}

// ---------------- kernels ----------------
__global__ void __launch_bounds__(256) k_qkv(const float* __restrict__ x, const float* __restrict__ w) {
    mma_nt_128x128(x, DIMC, w, DIMC, g_qkv, LDQKV, DIMC, 1.f, nullptr);
}
__global__ void __launch_bounds__(256) k_scores() {
    const int z = blockIdx.z, b = z / HEADS, h = z % HEADS;
    const float* q = g_qkv + (size_t)b * NN * LDQKV + h * HD;
    mma_nt_128x128(q, LDQKV, q + DIMC, LDQKV, g_S + (size_t)z * NN * NN, NN, HD, ATT_SCALE, nullptr);
}
__global__ void __launch_bounds__(128) k_av() {
    const int z = blockIdx.z, b = z / HEADS, h = z % HEADS;
    mma_nn_128x64<0>(g_S + (size_t)z * NN * NN, NN,
                     g_qkv + (size_t)b * NN * LDQKV + 2 * DIMC + h * HD, LDQKV, z, NN, nullptr);
}
__global__ void __launch_bounds__(128) k_aav(const float* __restrict__ lamb) {
    const int z = blockIdx.z;
    mma_nn_128x64<1>(g_S + (size_t)z * NN * NN, NN, g_Av + (size_t)z * NN * HD, HD, z, NN, lamb);
}
__global__ void __launch_bounds__(256) k_out(const float* __restrict__ w, const float* __restrict__ bias,
                                             float* __restrict__ out) {
    mma_nt_128x128(g_O, DIMC, w, DIMC, out, DIMC, DIMC, 1.f, bias);
}

// Fused: pre-softmax head mix (L) -> softmax -> post-softmax head mix (W), in-place on g_S.
__global__ void __launch_bounds__(256) k_mix(const float* __restrict__ Lw,
                                             const float* __restrict__ Lb,
                                             const float* __restrict__ Ww,
                                             const float* __restrict__ Wb)
{
    extern __shared__ float sm[];  // [12][1024]
    __shared__ float sL[144], sW[144], sbl[12], sbw[12];
    __shared__ float red[12][8];
    __shared__ float gmax[12], ginv[12];

    const int tid = threadIdx.x;
    const int b = blockIdx.x >> 10;
    const int n = blockIdx.x & 1023;

    if (tid < 144) { sL[tid] = Lw[tid]; sW[tid] = Ww[tid]; }
    if (tid < 12)  { sbl[tid] = Lb[tid]; sbw[tid] = Wb[tid]; }

    float* Sbase = g_S + (size_t)b * HEADS * NN * NN + (size_t)n * NN;

    for (int idx = tid; idx < HEADS * NN; idx += 256) {
        int h = idx >> 10, m = idx & 1023;
        sm[idx] = Sbase[(size_t)h * NN * NN + m];
    }
    __syncthreads();

    float lred[12];
#pragma unroll
    for (int g = 0; g < 12; g++) lred[g] = -1e30f;
    for (int m = tid; m < NN; m += 256) {
        float s[12];
#pragma unroll
        for (int h = 0; h < 12; h++) s[h] = sm[(h << 10) + m];
#pragma unroll
        for (int g = 0; g < 12; g++) {
            float t = sbl[g];
#pragma unroll
            for (int h = 0; h < 12; h++) t = fmaf(sL[g * 12 + h], s[h], t);
            sm[(g << 10) + m] = t;
            lred[g] = fmaxf(lred[g], t);
        }
    }
    const int lane = tid & 31, wrp = tid >> 5;
#pragma unroll
    for (int g = 0; g < 12; g++) {
        float v = lred[g];
#pragma unroll
        for (int o = 16; o; o >>= 1) v = fmaxf(v, __shfl_xor_sync(0xffffffffu, v, o));
        if (lane == 0) red[g][wrp] = v;
    }
    __syncthreads();
    if (tid < 12) {
        float v = red[tid][0];
#pragma unroll
        for (int w = 1; w < 8; w++) v = fmaxf(v, red[tid][w]);
        gmax[tid] = v;
    }
    __syncthreads();

#pragma unroll
    for (int g = 0; g < 12; g++) lred[g] = 0.f;
    for (int m = tid; m < NN; m += 256) {
#pragma unroll
        for (int g = 0; g < 12; g++) {
            float e = __expf(sm[(g << 10) + m] - gmax[g]);
            sm[(g << 10) + m] = e;
            lred[g] += e;
        }
    }
#pragma unroll
    for (int g = 0; g < 12; g++) {
        float v = lred[g];
#pragma unroll
        for (int o = 16; o; o >>= 1) v += __shfl_xor_sync(0xffffffffu, v, o);
        if (lane == 0) red[g][wrp] = v;
    }
    __syncthreads();
    if (tid < 12) {
        float v = red[tid][0];
#pragma unroll
        for (int w = 1; w < 8; w++) v += red[tid][w];
        ginv[tid] = 1.f / v;
    }
    __syncthreads();

    for (int m = tid; m < NN; m += 256) {
        float p[12];
#pragma unroll
        for (int h = 0; h < 12; h++) p[h] = sm[(h << 10) + m] * ginv[h];
#pragma unroll
        for (int g = 0; g < 12; g++) {
            float a = sbw[g];
#pragma unroll
            for (int h = 0; h < 12; h++) a = fmaf(sW[g * 12 + h], p[h], a);
            Sbase[(size_t)g * NN * NN + m] = a;
        }
    }
}

// ---------------- launch ----------------
extern "C" void kernel_launch(void* const* d_in, const int* in_sizes, int n_in,
                              void* d_out, int out_size)
{
    (void)in_sizes; (void)n_in; (void)out_size;
    const float* x      = (const float*)d_in[0];
    const float* qkv_w  = (const float*)d_in[1];
    const float* Lw     = (const float*)d_in[2];
    const float* Lb     = (const float*)d_in[3];
    const float* Ww     = (const float*)d_in[4];
    const float* Wb     = (const float*)d_in[5];
    const float* lamb   = (const float*)d_in[6];
    const float* Wout   = (const float*)d_in[7];
    const float* bout   = (const float*)d_in[8];
    float* out = (float*)d_out;

    cudaFuncSetAttribute(k_mix, cudaFuncAttributeMaxDynamicSharedMemorySize,
                         HEADS * NN * sizeof(float));

    k_qkv<<<dim3(LDQKV / 128, (NB * NN) / 128), 256>>>(x, qkv_w);
    k_scores<<<dim3(NN / 128, NN / 128, NB * HEADS), 256>>>();
    k_mix<<<NB * NN, 256, HEADS * NN * sizeof(float)>>>(Lw, Lb, Ww, Wb);
    k_av<<<dim3(1, NN / 128, NB * HEADS), 128>>>();
    k_aav<<<dim3(1, NN / 128, NB * HEADS), 128>>>(lamb);
    k_out<<<dim3(DIMC / 128, (NB * NN) / 128), 256>>>(Wout, bout, out);
}

// round 4
// speedup vs baseline: 1.8717x; 1.8717x over previous
#include <cuda_runtime.h>
#include <cuda_fp16.h>
#include <stdint.h>

#define HEADS 12
#define HD 64
#define DIMC 768
#define NB 4
#define NN 1024
#define LDQKV (3 * DIMC)
#define ATT_SCALE 0.125f

// ---------------- global scratch: fp16 hi/lo planes ----------------
__device__ __half g_xh[(size_t)NB * NN * DIMC],  g_xl[(size_t)NB * NN * DIMC];
__device__ __half g_wqh[(size_t)3 * DIMC * DIMC], g_wql[(size_t)3 * DIMC * DIMC];
__device__ __half g_woh[(size_t)DIMC * DIMC],     g_wol[(size_t)DIMC * DIMC];
__device__ __half g_qkvh[(size_t)NB * NN * LDQKV], g_qkvl[(size_t)NB * NN * LDQKV];
__device__ float  g_S[(size_t)NB * HEADS * NN * NN];
__device__ __half g_Ah[(size_t)NB * HEADS * NN * NN], g_Al[(size_t)NB * HEADS * NN * NN];
__device__ __half g_Avh[(size_t)NB * HEADS * NN * HD], g_Avl[(size_t)NB * HEADS * NN * HD];
__device__ __half g_Oh[(size_t)NB * NN * DIMC],   g_Ol[(size_t)NB * NN * DIMC];

// ---------------- helpers ----------------
__device__ __forceinline__ void splitf(float v, __half &h, __half &l) {
    h = __float2half_rn(v);
    l = __float2half_rn(v - __half2float(h));
}
__device__ __forceinline__ void mma16816(float *c, const uint32_t *a, const uint32_t *b) {
    asm volatile(
        "mma.sync.aligned.m16n8k16.row.col.f32.f16.f16.f32 "
        "{%0,%1,%2,%3},{%4,%5,%6,%7},{%8,%9},{%0,%1,%2,%3};"
        : "+f"(c[0]), "+f"(c[1]), "+f"(c[2]), "+f"(c[3])
        : "r"(a[0]), "r"(a[1]), "r"(a[2]), "r"(a[3]), "r"(b[0]), "r"(b[1]));
}
__device__ __forceinline__ void ldm_x4(uint32_t (&r)[4], uint32_t a) {
    asm volatile("ldmatrix.sync.aligned.m8n8.x4.shared.b16 {%0,%1,%2,%3}, [%4];"
                 : "=r"(r[0]), "=r"(r[1]), "=r"(r[2]), "=r"(r[3]) : "r"(a));
}
__device__ __forceinline__ void ldm_x2(uint32_t (&r)[2], uint32_t a) {
    asm volatile("ldmatrix.sync.aligned.m8n8.x2.shared.b16 {%0,%1}, [%2];"
                 : "=r"(r[0]), "=r"(r[1]) : "r"(a));
}
__device__ __forceinline__ void ldm_x2t(uint32_t (&r)[2], uint32_t a) {
    asm volatile("ldmatrix.sync.aligned.m8n8.x2.trans.shared.b16 {%0,%1}, [%2];"
                 : "=r"(r[0]), "=r"(r[1]) : "r"(a));
}
__device__ __forceinline__ void cpa16(uint32_t s, const void *g) {
    asm volatile("cp.async.cg.shared.global [%0], [%1], 16;" :: "r"(s), "l"(g));
}
__device__ __forceinline__ void cpa_commit() { asm volatile("cp.async.commit_group;"); }
__device__ __forceinline__ void cpa_wait1()  { asm volatile("cp.async.wait_group 1;"); }
__device__ __forceinline__ void cpa_wait0()  { asm volatile("cp.async.wait_group 0;"); }

// ================= NT engine: BM=128, BN=128, BK=32, 256 thr, 8 warps (2x4) =================
// Smem stage (bytes): Ah 0, Al 10240, Bh 20480, Bl 30720; stride 40960; total 81920.
// Row stride 40 halves (80B) -> ldmatrix conflict-free.
__device__ __forceinline__ void gemm_nt(
    const __half* Agh, const __half* Agl, int lda,
    const __half* Bgh, const __half* Bgl, int ldb,
    int K, float (&acc)[4][4][4])
{
    extern __shared__ __align__(16) __half smx[];
    const uint32_t sb = (uint32_t)__cvta_generic_to_shared(smx);
    const int t = threadIdx.x, lane = t & 31, wid = t >> 5;
    const int wm = wid >> 2, wn = wid & 3;
    const int r = t >> 1, ch = (t & 1) * 2;    // 2 chunks of 8 halves per thread per plane

    const __half* pAh = Agh + (size_t)r * lda + ch * 8;
    const __half* pAl = Agl + (size_t)r * lda + ch * 8;
    const __half* pBh = Bgh + (size_t)r * ldb + ch * 8;
    const __half* pBl = Bgl + (size_t)r * ldb + ch * 8;
    const uint32_t soff = (uint32_t)(r * 40 + ch * 8) * 2;

    const int nst = K / 32;
    // issue stage st from k-offset k0
    auto issue = [&](int st, int k0) {
        uint32_t s0 = sb + st * 40960 + soff;
        cpa16(s0,             pAh + k0); cpa16(s0 + 16,         pAh + k0 + 8);
        cpa16(s0 + 10240,     pAl + k0); cpa16(s0 + 10240 + 16, pAl + k0 + 8);
        cpa16(s0 + 20480,     pBh + k0); cpa16(s0 + 20480 + 16, pBh + k0 + 8);
        cpa16(s0 + 30720,     pBl + k0); cpa16(s0 + 30720 + 16, pBl + k0 + 8);
        cpa_commit();
    };

    issue(0, 0);
    int p = 0;
    for (int i = 0; i < nst; i++) {
        if (i + 1 < nst) { issue(p ^ 1, (i + 1) * 32); cpa_wait1(); }
        else cpa_wait0();
        __syncthreads();
        const uint32_t sA = sb + p * 40960;
        const uint32_t sB = sA + 20480;
#pragma unroll
        for (int s2 = 0; s2 < 2; s2++) {
            uint32_t ah[4][4], al[4][4];
#pragma unroll
            for (int mf = 0; mf < 4; mf++) {
                const int m0 = wm * 64 + mf * 16;
                const uint32_t ad = sA + (uint32_t)((m0 + (lane & 15)) * 40) * 2
                                  + s2 * 32 + ((lane >> 4) & 1) * 16;
                ldm_x4(ah[mf], ad);
                ldm_x4(al[mf], ad + 10240);
            }
#pragma unroll
            for (int nf = 0; nf < 4; nf++) {
                const int n0 = wn * 32 + nf * 8;
                const uint32_t bd = sB + (uint32_t)((n0 + (lane & 7)) * 40) * 2
                                  + s2 * 32 + (((lane & 15) >> 3) & 1) * 16;
                uint32_t bh[2], bl[2];
                ldm_x2(bh, bd);
                ldm_x2(bl, bd + 10240);
#pragma unroll
                for (int mf = 0; mf < 4; mf++) {
                    mma16816(acc[mf][nf], al[mf], bh);
                    mma16816(acc[mf][nf], ah[mf], bl);
                    mma16816(acc[mf][nf], ah[mf], bh);
                }
            }
        }
        __syncthreads();
        p ^= 1;
    }
}

// ================= NN engine: BM=128, BN=64, BK=32, 256 thr, 8 warps (2x4, warp 64x16) =================
// Smem stage (bytes): Ah 0, Al 10240, Bh 20480, Bl 25088; stride 29696; total 59392.
// B stored [k][n], stride 72 halves (144B), fragments via ldmatrix.trans.
__device__ __forceinline__ void gemm_nn(
    const __half* Agh, const __half* Agl, int lda,
    const __half* Bgh, const __half* Bgl, int ldb,
    int K, float (&acc)[4][2][4])
{
    extern __shared__ __align__(16) __half smx[];
    const uint32_t sb = (uint32_t)__cvta_generic_to_shared(smx);
    const int t = threadIdx.x, lane = t & 31, wid = t >> 5;
    const int wm = wid >> 2, wn = wid & 3;
    const int r = t >> 1, ch = (t & 1) * 2;
    const int kr = t >> 3, nch = t & 7;        // B: 1 chunk per plane per thread

    const __half* pAh = Agh + (size_t)r * lda + ch * 8;
    const __half* pAl = Agl + (size_t)r * lda + ch * 8;
    const __half* pBh = Bgh + (size_t)kr * ldb + nch * 8;
    const __half* pBl = Bgl + (size_t)kr * ldb + nch * 8;
    const uint32_t aoff = (uint32_t)(r * 40 + ch * 8) * 2;
    const uint32_t boff = (uint32_t)(kr * 72 + nch * 8) * 2;

    const int nst = K / 32;
    auto issue = [&](int st, int k0) {
        uint32_t s0 = sb + st * 29696;
        cpa16(s0 + aoff,              pAh + k0); cpa16(s0 + aoff + 16,         pAh + k0 + 8);
        cpa16(s0 + 10240 + aoff,      pAl + k0); cpa16(s0 + 10240 + aoff + 16, pAl + k0 + 8);
        cpa16(s0 + 20480 + boff, pBh + (size_t)k0 * ldb);
        cpa16(s0 + 25088 + boff, pBl + (size_t)k0 * ldb);
        cpa_commit();
    };

    issue(0, 0);
    int p = 0;
    for (int i = 0; i < nst; i++) {
        if (i + 1 < nst) { issue(p ^ 1, (i + 1) * 32); cpa_wait1(); }
        else cpa_wait0();
        __syncthreads();
        const uint32_t sA = sb + p * 29696;
        const uint32_t sB = sA + 20480;
#pragma unroll
        for (int s2 = 0; s2 < 2; s2++) {
            uint32_t ah[4][4], al[4][4];
#pragma unroll
            for (int mf = 0; mf < 4; mf++) {
                const int m0 = wm * 64 + mf * 16;
                const uint32_t ad = sA + (uint32_t)((m0 + (lane & 15)) * 40) * 2
                                  + s2 * 32 + ((lane >> 4) & 1) * 16;
                ldm_x4(ah[mf], ad);
                ldm_x4(al[mf], ad + 10240);
            }
#pragma unroll
            for (int nf = 0; nf < 2; nf++) {
                const int n0 = wn * 16 + nf * 8;
                const int krow = s2 * 16 + ((lane & 15) >> 3) * 8 + (lane & 7);
                const uint32_t bd = sB + (uint32_t)(krow * 72 + n0) * 2;
                uint32_t bh[2], bl[2];
                ldm_x2t(bh, bd);
                ldm_x2t(bl, bd + 4608);
#pragma unroll
                for (int mf = 0; mf < 4; mf++) {
                    mma16816(acc[mf][nf], al[mf], bh);
                    mma16816(acc[mf][nf], ah[mf], bl);
                    mma16816(acc[mf][nf], ah[mf], bh);
                }
            }
        }
        __syncthreads();
        p ^= 1;
    }
}

// ---------------- kernels ----------------
__global__ void __launch_bounds__(256) k_split(const float* __restrict__ s,
                                               __half* __restrict__ dh,
                                               __half* __restrict__ dl, int n4)
{
    int i = blockIdx.x * 256 + threadIdx.x;
    if (i >= n4) return;
    float4 v = ((const float4*)s)[i];
    __half h0, h1, h2, h3, l0, l1, l2, l3;
    splitf(v.x, h0, l0); splitf(v.y, h1, l1); splitf(v.z, h2, l2); splitf(v.w, h3, l3);
    ((__half2*)dh)[i * 2]     = __halves2half2(h0, h1);
    ((__half2*)dh)[i * 2 + 1] = __halves2half2(h2, h3);
    ((__half2*)dl)[i * 2]     = __halves2half2(l0, l1);
    ((__half2*)dl)[i * 2 + 1] = __halves2half2(l2, l3);
}

__global__ void __launch_bounds__(256, 2) k_qkv()
{
    const int row0 = blockIdx.y * 128, col0 = blockIdx.x * 128;
    float acc[4][4][4] = {};
    gemm_nt(g_xh + (size_t)row0 * DIMC, g_xl + (size_t)row0 * DIMC, DIMC,
            g_wqh + (size_t)col0 * DIMC, g_wql + (size_t)col0 * DIMC, DIMC,
            DIMC, acc);
    const int lane = threadIdx.x & 31, wid = threadIdx.x >> 5;
    const int wm = wid >> 2, wn = wid & 3, g = lane >> 2, tig = lane & 3;
#pragma unroll
    for (int mf = 0; mf < 4; mf++) {
        const int row = row0 + wm * 64 + mf * 16 + g;
#pragma unroll
        for (int nf = 0; nf < 4; nf++) {
            const int col = col0 + wn * 32 + nf * 8 + tig * 2;
            __half h0, h1, l0, l1;
            splitf(acc[mf][nf][0], h0, l0); splitf(acc[mf][nf][1], h1, l1);
            *(__half2*)&g_qkvh[(size_t)row * LDQKV + col] = __halves2half2(h0, h1);
            *(__half2*)&g_qkvl[(size_t)row * LDQKV + col] = __halves2half2(l0, l1);
            splitf(acc[mf][nf][2], h0, l0); splitf(acc[mf][nf][3], h1, l1);
            *(__half2*)&g_qkvh[(size_t)(row + 8) * LDQKV + col] = __halves2half2(h0, h1);
            *(__half2*)&g_qkvl[(size_t)(row + 8) * LDQKV + col] = __halves2half2(l0, l1);
        }
    }
}

__global__ void __launch_bounds__(256, 2) k_scores()
{
    const int z = blockIdx.z, b = z / HEADS, h = z % HEADS;
    const int row0 = blockIdx.y * 128, col0 = blockIdx.x * 128;
    const size_t qo = (size_t)b * NN * LDQKV + h * HD;
    float acc[4][4][4] = {};
    gemm_nt(g_qkvh + qo + (size_t)row0 * LDQKV, g_qkvl + qo + (size_t)row0 * LDQKV, LDQKV,
            g_qkvh + qo + DIMC + (size_t)col0 * LDQKV, g_qkvl + qo + DIMC + (size_t)col0 * LDQKV, LDQKV,
            HD, acc);
    const int lane = threadIdx.x & 31, wid = threadIdx.x >> 5;
    const int wm = wid >> 2, wn = wid & 3, g = lane >> 2, tig = lane & 3;
    float* S = g_S + (size_t)z * NN * NN;
#pragma unroll
    for (int mf = 0; mf < 4; mf++) {
        const int row = row0 + wm * 64 + mf * 16 + g;
#pragma unroll
        for (int nf = 0; nf < 4; nf++) {
            const int col = col0 + wn * 32 + nf * 8 + tig * 2;
            *(float2*)&S[(size_t)row * NN + col] =
                make_float2(acc[mf][nf][0] * ATT_SCALE, acc[mf][nf][1] * ATT_SCALE);
            *(float2*)&S[(size_t)(row + 8) * NN + col] =
                make_float2(acc[mf][nf][2] * ATT_SCALE, acc[mf][nf][3] * ATT_SCALE);
        }
    }
}

__global__ void __launch_bounds__(256, 3) k_av()
{
    const int z = blockIdx.z, b = z / HEADS, h = z % HEADS;
    const int row0 = blockIdx.y * 128;
    const size_t ao = (size_t)z * NN * NN + (size_t)row0 * NN;
    const size_t vo = (size_t)b * NN * LDQKV + 2 * DIMC + h * HD;
    float acc[4][2][4] = {};
    gemm_nn(g_Ah + ao, g_Al + ao, NN, g_qkvh + vo, g_qkvl + vo, LDQKV, NN, acc);
    const int lane = threadIdx.x & 31, wid = threadIdx.x >> 5;
    const int wm = wid >> 2, wn = wid & 3, g = lane >> 2, tig = lane & 3;
    __half* Avh = g_Avh + (size_t)z * NN * HD;
    __half* Avl = g_Avl + (size_t)z * NN * HD;
#pragma unroll
    for (int mf = 0; mf < 4; mf++) {
        const int row = row0 + wm * 64 + mf * 16 + g;
#pragma unroll
        for (int nf = 0; nf < 2; nf++) {
            const int col = wn * 16 + nf * 8 + tig * 2;
            __half h0, h1, l0, l1;
            splitf(acc[mf][nf][0], h0, l0); splitf(acc[mf][nf][1], h1, l1);
            *(__half2*)&Avh[(size_t)row * HD + col] = __halves2half2(h0, h1);
            *(__half2*)&Avl[(size_t)row * HD + col] = __halves2half2(l0, l1);
            splitf(acc[mf][nf][2], h0, l0); splitf(acc[mf][nf][3], h1, l1);
            *(__half2*)&Avh[(size_t)(row + 8) * HD + col] = __halves2half2(h0, h1);
            *(__half2*)&Avl[(size_t)(row + 8) * HD + col] = __halves2half2(l0, l1);
        }
    }
}

__global__ void __launch_bounds__(256, 3) k_aav(const float* __restrict__ lamb)
{
    const int z = blockIdx.z, b = z / HEADS, h = z % HEADS;
    const int row0 = blockIdx.y * 128;
    const size_t ao = (size_t)z * NN * NN + (size_t)row0 * NN;
    const size_t avo = (size_t)z * NN * HD;
    float acc[4][2][4] = {};
    gemm_nn(g_Ah + ao, g_Al + ao, NN, g_Avh + avo, g_Avl + avo, HD, NN, acc);
    const float lam = lamb[h];
    const float c1 = 1.f - 2.f * lam, c3 = 3.f * lam;
    const int lane = threadIdx.x & 31, wid = threadIdx.x >> 5;
    const int wm = wid >> 2, wn = wid & 3, g = lane >> 2, tig = lane & 3;
#pragma unroll
    for (int mf = 0; mf < 4; mf++) {
#pragma unroll
        for (int nf = 0; nf < 2; nf++) {
            const int col = wn * 16 + nf * 8 + tig * 2;
#pragma unroll
            for (int half_ = 0; half_ < 2; half_++) {
                const int row = row0 + wm * 64 + mf * 16 + g + half_ * 8;
                __half2 avh = *(const __half2*)&g_Avh[avo + (size_t)row * HD + col];
                __half2 avl = *(const __half2*)&g_Avl[avo + (size_t)row * HD + col];
                float av0 = __half2float(avh.x) + __half2float(avl.x);
                float av1 = __half2float(avh.y) + __half2float(avl.y);
                float o0 = fmaf(c3, acc[mf][nf][half_ * 2],     c1 * av0);
                float o1 = fmaf(c3, acc[mf][nf][half_ * 2 + 1], c1 * av1);
                __half h0, h1, l0, l1;
                splitf(o0, h0, l0); splitf(o1, h1, l1);
                const size_t oi = ((size_t)b * NN + row) * DIMC + h * HD + col;
                *(__half2*)&g_Oh[oi] = __halves2half2(h0, h1);
                *(__half2*)&g_Ol[oi] = __halves2half2(l0, l1);
            }
        }
    }
}

__global__ void __launch_bounds__(256, 2) k_out(const float* __restrict__ bias,
                                                float* __restrict__ out)
{
    const int row0 = blockIdx.y * 128, col0 = blockIdx.x * 128;
    float acc[4][4][4] = {};
    gemm_nt(g_Oh + (size_t)row0 * DIMC, g_Ol + (size_t)row0 * DIMC, DIMC,
            g_woh + (size_t)col0 * DIMC, g_wol + (size_t)col0 * DIMC, DIMC,
            DIMC, acc);
    const int lane = threadIdx.x & 31, wid = threadIdx.x >> 5;
    const int wm = wid >> 2, wn = wid & 3, g = lane >> 2, tig = lane & 3;
#pragma unroll
    for (int mf = 0; mf < 4; mf++) {
        const int row = row0 + wm * 64 + mf * 16 + g;
#pragma unroll
        for (int nf = 0; nf < 4; nf++) {
            const int col = col0 + wn * 32 + nf * 8 + tig * 2;
            const float b0 = bias[col], b1 = bias[col + 1];
            *(float2*)&out[(size_t)row * DIMC + col] =
                make_float2(acc[mf][nf][0] + b0, acc[mf][nf][1] + b1);
            *(float2*)&out[(size_t)(row + 8) * DIMC + col] =
                make_float2(acc[mf][nf][2] + b0, acc[mf][nf][3] + b1);
        }
    }
}

// Fused: L-mix -> softmax -> W-mix; reads g_S fp32, writes A as fp16 hi/lo planes.
__global__ void __launch_bounds__(256) k_mix(const float* __restrict__ Lw,
                                             const float* __restrict__ Lb,
                                             const float* __restrict__ Ww,
                                             const float* __restrict__ Wb)
{
    extern __shared__ float sm[];  // [12][1024]
    __shared__ float sL[144], sW[144], sbl[12], sbw[12];
    __shared__ float red[12][8];
    __shared__ float gmax[12], ginv[12];

    const int tid = threadIdx.x;
    const int b = blockIdx.x >> 10;
    const int n = blockIdx.x & 1023;

    if (tid < 144) { sL[tid] = Lw[tid]; sW[tid] = Ww[tid]; }
    if (tid < 12)  { sbl[tid] = Lb[tid]; sbw[tid] = Wb[tid]; }

    const float* Sbase = g_S + (size_t)b * HEADS * NN * NN + (size_t)n * NN;

    for (int idx = tid; idx < HEADS * NN; idx += 256) {
        int h = idx >> 10, m = idx & 1023;
        sm[idx] = Sbase[(size_t)h * NN * NN + m];
    }
    __syncthreads();

    float lred[12];
#pragma unroll
    for (int g = 0; g < 12; g++) lred[g] = -1e30f;
    for (int m = tid; m < NN; m += 256) {
        float s[12];
#pragma unroll
        for (int h = 0; h < 12; h++) s[h] = sm[(h << 10) + m];
#pragma unroll
        for (int g = 0; g < 12; g++) {
            float t = sbl[g];
#pragma unroll
            for (int h = 0; h < 12; h++) t = fmaf(sL[g * 12 + h], s[h], t);
            sm[(g << 10) + m] = t;
            lred[g] = fmaxf(lred[g], t);
        }
    }
    const int lane = tid & 31, wrp = tid >> 5;
#pragma unroll
    for (int g = 0; g < 12; g++) {
        float v = lred[g];
#pragma unroll
        for (int o = 16; o; o >>= 1) v = fmaxf(v, __shfl_xor_sync(0xffffffffu, v, o));
        if (lane == 0) red[g][wrp] = v;
    }
    __syncthreads();
    if (tid < 12) {
        float v = red[tid][0];
#pragma unroll
        for (int w = 1; w < 8; w++) v = fmaxf(v, red[tid][w]);
        gmax[tid] = v;
    }
    __syncthreads();

#pragma unroll
    for (int g = 0; g < 12; g++) lred[g] = 0.f;
    for (int m = tid; m < NN; m += 256) {
#pragma unroll
        for (int g = 0; g < 12; g++) {
            float e = __expf(sm[(g << 10) + m] - gmax[g]);
            sm[(g << 10) + m] = e;
            lred[g] += e;
        }
    }
#pragma unroll
    for (int g = 0; g < 12; g++) {
        float v = lred[g];
#pragma unroll
        for (int o = 16; o; o >>= 1) v += __shfl_xor_sync(0xffffffffu, v, o);
        if (lane == 0) red[g][wrp] = v;
    }
    __syncthreads();
    if (tid < 12) {
        float v = red[tid][0];
#pragma unroll
        for (int w = 1; w < 8; w++) v += red[tid][w];
        ginv[tid] = 1.f / v;
    }
    __syncthreads();

    const size_t abase = (size_t)b * HEADS * NN * NN + (size_t)n * NN;
    for (int m = tid; m < NN; m += 256) {
        float p[12];
#pragma unroll
        for (int h = 0; h < 12; h++) p[h] = sm[(h << 10) + m] * ginv[h];
#pragma unroll
        for (int g = 0; g < 12; g++) {
            float a = sbw[g];
#pragma unroll
            for (int h = 0; h < 12; h++) a = fmaf(sW[g * 12 + h], p[h], a);
            __half hh, ll;
            splitf(a, hh, ll);
            g_Ah[abase + (size_t)g * NN * NN + m] = hh;
            g_Al[abase + (size_t)g * NN * NN + m] = ll;
        }
    }
}

// ---------------- launch ----------------
extern "C" void kernel_launch(void* const* d_in, const int* in_sizes, int n_in,
                              void* d_out, int out_size)
{
    (void)in_sizes; (void)n_in; (void)out_size;
    const float* x      = (const float*)d_in[0];
    const float* qkv_w  = (const float*)d_in[1];
    const float* Lw     = (const float*)d_in[2];
    const float* Lb     = (const float*)d_in[3];
    const float* Ww     = (const float*)d_in[4];
    const float* Wb     = (const float*)d_in[5];
    const float* lamb   = (const float*)d_in[6];
    const float* Wout   = (const float*)d_in[7];
    const float* bout   = (const float*)d_in[8];
    float* out = (float*)d_out;

    static int configured = 0;
    const int NT_SMEM = 81920, NN_SMEM = 59392, MIX_SMEM = HEADS * NN * (int)sizeof(float);
    cudaFuncSetAttribute(k_qkv,    cudaFuncAttributeMaxDynamicSharedMemorySize, NT_SMEM);
    cudaFuncSetAttribute(k_scores, cudaFuncAttributeMaxDynamicSharedMemorySize, NT_SMEM);
    cudaFuncSetAttribute(k_out,    cudaFuncAttributeMaxDynamicSharedMemorySize, NT_SMEM);
    cudaFuncSetAttribute(k_av,     cudaFuncAttributeMaxDynamicSharedMemorySize, NN_SMEM);
    cudaFuncSetAttribute(k_aav,    cudaFuncAttributeMaxDynamicSharedMemorySize, NN_SMEM);
    cudaFuncSetAttribute(k_mix,    cudaFuncAttributeMaxDynamicSharedMemorySize, MIX_SMEM);
    (void)configured;

    __half *xh, *xl, *wqh, *wql, *woh, *wol;
    cudaGetSymbolAddress((void**)&xh,  g_xh);  cudaGetSymbolAddress((void**)&xl,  g_xl);
    cudaGetSymbolAddress((void**)&wqh, g_wqh); cudaGetSymbolAddress((void**)&wql, g_wql);
    cudaGetSymbolAddress((void**)&woh, g_woh); cudaGetSymbolAddress((void**)&wol, g_wol);

    // 0) split inputs to fp16 hi/lo planes
    {
        int n4 = NB * NN * DIMC / 4;
        k_split<<<(n4 + 255) / 256, 256>>>(x, xh, xl, n4);
        n4 = 3 * DIMC * DIMC / 4;
        k_split<<<(n4 + 255) / 256, 256>>>(qkv_w, wqh, wql, n4);
        n4 = DIMC * DIMC / 4;
        k_split<<<(n4 + 255) / 256, 256>>>(Wout, woh, wol, n4);
    }
    // 1) qkv
    k_qkv<<<dim3(LDQKV / 128, (NB * NN) / 128), 256, NT_SMEM>>>();
    // 2) scores
    k_scores<<<dim3(NN / 128, NN / 128, NB * HEADS), 256, NT_SMEM>>>();
    // 3) mix + softmax + mix (writes A planes)
    k_mix<<<NB * NN, 256, MIX_SMEM>>>(Lw, Lb, Ww, Wb);
    // 4) Av = A @ v
    k_av<<<dim3(1, NN / 128, NB * HEADS), 256, NN_SMEM>>>();
    // 5) O = (1-2λ)Av + 3λ A@Av
    k_aav<<<dim3(1, NN / 128, NB * HEADS), 256, NN_SMEM>>>(lamb);
    // 6) final projection
    k_out<<<dim3(DIMC / 128, (NB * NN) / 128), 256, NT_SMEM>>>(bout, out);
}

// round 7
// speedup vs baseline: 1.8877x; 1.0085x over previous
#include <cuda_runtime.h>
#include <cuda_fp16.h>
#include <stdint.h>

#define HEADS 12
#define HD 64
#define DIMC 768
#define NB 4
#define NN 1024
#define LDQKV (3 * DIMC)
#define ATT_SCALE 0.125f

// ---------------- global scratch: fp16 hi/lo planes ----------------
__device__ __half g_xh[(size_t)NB * NN * DIMC],  g_xl[(size_t)NB * NN * DIMC];
__device__ __half g_wqh[(size_t)3 * DIMC * DIMC], g_wql[(size_t)3 * DIMC * DIMC];
__device__ __half g_woh[(size_t)DIMC * DIMC],     g_wol[(size_t)DIMC * DIMC];
__device__ __half g_qkvh[(size_t)NB * NN * LDQKV], g_qkvl[(size_t)NB * NN * LDQKV];
__device__ float  g_S[(size_t)NB * HEADS * NN * NN];
__device__ __half g_Ah[(size_t)NB * HEADS * NN * NN], g_Al[(size_t)NB * HEADS * NN * NN];
__device__ __half g_Avh[(size_t)NB * HEADS * NN * HD], g_Avl[(size_t)NB * HEADS * NN * HD];
__device__ __half g_Oh[(size_t)NB * NN * DIMC],   g_Ol[(size_t)NB * NN * DIMC];

// ---------------- helpers ----------------
__device__ __forceinline__ void splitf(float v, __half &h, __half &l) {
    h = __float2half_rn(v);
    l = __float2half_rn(v - __half2float(h));
}
__device__ __forceinline__ void mma16816(float *c, const uint32_t *a, const uint32_t *b) {
    asm volatile(
        "mma.sync.aligned.m16n8k16.row.col.f32.f16.f16.f32 "
        "{%0,%1,%2,%3},{%4,%5,%6,%7},{%8,%9},{%0,%1,%2,%3};"
        : "+f"(c[0]), "+f"(c[1]), "+f"(c[2]), "+f"(c[3])
        : "r"(a[0]), "r"(a[1]), "r"(a[2]), "r"(a[3]), "r"(b[0]), "r"(b[1]));
}
__device__ __forceinline__ void ldm_x4(uint32_t (&r)[4], uint32_t a) {
    asm volatile("ldmatrix.sync.aligned.m8n8.x4.shared.b16 {%0,%1,%2,%3}, [%4];"
                 : "=r"(r[0]), "=r"(r[1]), "=r"(r[2]), "=r"(r[3]) : "r"(a));
}
__device__ __forceinline__ void ldm_x2(uint32_t (&r)[2], uint32_t a) {
    asm volatile("ldmatrix.sync.aligned.m8n8.x2.shared.b16 {%0,%1}, [%2];"
                 : "=r"(r[0]), "=r"(r[1]) : "r"(a));
}
__device__ __forceinline__ void ldm_x2t(uint32_t (&r)[2], uint32_t a) {
    asm volatile("ldmatrix.sync.aligned.m8n8.x2.trans.shared.b16 {%0,%1}, [%2];"
                 : "=r"(r[0]), "=r"(r[1]) : "r"(a));
}
__device__ __forceinline__ void cpa16(uint32_t s, const void *g) {
    asm volatile("cp.async.cg.shared.global [%0], [%1], 16;" :: "r"(s), "l"(g));
}
__device__ __forceinline__ void cpa_commit() { asm volatile("cp.async.commit_group;"); }

// ================= NT engine: BM=128, BN=128, BK=16, 4-stage, 256 thr, 8 warps (2x4) =================
// Row stride 48B (16 halves content + 8 pad): 16B-aligned cp.async, conflict-free ldmatrix
// (row r -> banks 12r..12r+3 mod 32; 8 rows partition all 32 banks).
// Stage layout (bytes): Ah 0, Al 6144, Bh 12288, Bl 18432; stride 24576; total 98304.
__device__ __forceinline__ void gemm_nt(
    const __half* Agh, const __half* Agl, int lda,
    const __half* Bgh, const __half* Bgl, int ldb,
    int K, float (&acc)[4][4][4])
{
    extern __shared__ __align__(16) __half smx[];
    const uint32_t sb = (uint32_t)__cvta_generic_to_shared(smx);
    const int t = threadIdx.x, lane = t & 31, wid = t >> 5;
    const int wm = wid >> 2, wn = wid & 3;
    const int r = t >> 1, s16 = t & 1;     // one 16B segment per thread per plane

    const __half* pAh = Agh + (size_t)r * lda + s16 * 8;
    const __half* pAl = Agl + (size_t)r * lda + s16 * 8;
    const __half* pBh = Bgh + (size_t)r * ldb + s16 * 8;
    const __half* pBl = Bgl + (size_t)r * ldb + s16 * 8;
    const uint32_t soff = (uint32_t)(r * 48 + s16 * 16);

    const int nst = K >> 4;
    auto issue = [&](int i) {
        const uint32_t s0 = sb + (uint32_t)(i & 3) * 24576 + soff;
        const int k0 = i * 16;
        cpa16(s0,         pAh + k0);
        cpa16(s0 + 6144,  pAl + k0);
        cpa16(s0 + 12288, pBh + k0);
        cpa16(s0 + 18432, pBl + k0);
        cpa_commit();
    };

    issue(0);
    if (nst > 1) issue(1);
    if (nst > 2) issue(2);

    for (int i = 0; i < nst; i++) {
        if (i + 3 < nst) {
            issue(i + 3);
            asm volatile("cp.async.wait_group 3;");
        } else {
            const int rem = nst - 1 - i;
            if (rem == 2)      asm volatile("cp.async.wait_group 2;");
            else if (rem == 1) asm volatile("cp.async.wait_group 1;");
            else               asm volatile("cp.async.wait_group 0;");
        }
        __syncthreads();
        const uint32_t sA = sb + (uint32_t)(i & 3) * 24576;
        const uint32_t sB = sA + 12288;
        uint32_t ah[4][4], al[4][4];
#pragma unroll
        for (int mf = 0; mf < 4; mf++) {
            const int m0 = wm * 64 + mf * 16;
            const uint32_t ad = sA + (uint32_t)((m0 + (lane & 15)) * 48) + ((lane >> 4) & 1) * 16;
            ldm_x4(ah[mf], ad);
            ldm_x4(al[mf], ad + 6144);
        }
#pragma unroll
        for (int nf = 0; nf < 4; nf++) {
            const int n0 = wn * 32 + nf * 8;
            const uint32_t bd = sB + (uint32_t)((n0 + (lane & 7)) * 48) + (((lane & 15) >> 3) & 1) * 16;
            uint32_t bh[2], bl[2];
            ldm_x2(bh, bd);
            ldm_x2(bl, bd + 6144);
#pragma unroll
            for (int mf = 0; mf < 4; mf++) {
                mma16816(acc[mf][nf], al[mf], bh);
                mma16816(acc[mf][nf], ah[mf], bl);
                mma16816(acc[mf][nf], ah[mf], bh);
            }
        }
        __syncthreads();
    }
}

// ================= NN engine: BM=128, BN=64, BK=32, 2-stage, 256 thr (R4-proven) =================
__device__ __forceinline__ void gemm_nn(
    const __half* Agh, const __half* Agl, int lda,
    const __half* Bgh, const __half* Bgl, int ldb,
    int K, float (&acc)[4][2][4])
{
    extern __shared__ __align__(16) __half smx[];
    const uint32_t sb = (uint32_t)__cvta_generic_to_shared(smx);
    const int t = threadIdx.x, lane = t & 31, wid = t >> 5;
    const int wm = wid >> 2, wn = wid & 3;
    const int r = t >> 1, ch = (t & 1) * 2;
    const int kr = t >> 3, nch = t & 7;

    const __half* pAh = Agh + (size_t)r * lda + ch * 8;
    const __half* pAl = Agl + (size_t)r * lda + ch * 8;
    const __half* pBh = Bgh + (size_t)kr * ldb + nch * 8;
    const __half* pBl = Bgl + (size_t)kr * ldb + nch * 8;
    const uint32_t aoff = (uint32_t)(r * 40 + ch * 8) * 2;
    const uint32_t boff = (uint32_t)(kr * 72 + nch * 8) * 2;

    const int nst = K / 32;
    auto issue = [&](int st, int k0) {
        uint32_t s0 = sb + st * 29696;
        cpa16(s0 + aoff,              pAh + k0); cpa16(s0 + aoff + 16,         pAh + k0 + 8);
        cpa16(s0 + 10240 + aoff,      pAl + k0); cpa16(s0 + 10240 + aoff + 16, pAl + k0 + 8);
        cpa16(s0 + 20480 + boff, pBh + (size_t)k0 * ldb);
        cpa16(s0 + 25088 + boff, pBl + (size_t)k0 * ldb);
        cpa_commit();
    };

    issue(0, 0);
    int p = 0;
    for (int i = 0; i < nst; i++) {
        if (i + 1 < nst) { issue(p ^ 1, (i + 1) * 32); asm volatile("cp.async.wait_group 1;"); }
        else asm volatile("cp.async.wait_group 0;");
        __syncthreads();
        const uint32_t sA = sb + p * 29696;
        const uint32_t sB = sA + 20480;
#pragma unroll
        for (int s2 = 0; s2 < 2; s2++) {
            uint32_t ah[4][4], al[4][4];
#pragma unroll
            for (int mf = 0; mf < 4; mf++) {
                const int m0 = wm * 64 + mf * 16;
                const uint32_t ad = sA + (uint32_t)((m0 + (lane & 15)) * 40) * 2
                                  + s2 * 32 + ((lane >> 4) & 1) * 16;
                ldm_x4(ah[mf], ad);
                ldm_x4(al[mf], ad + 10240);
            }
#pragma unroll
            for (int nf = 0; nf < 2; nf++) {
                const int n0 = wn * 16 + nf * 8;
                const int krow = s2 * 16 + ((lane & 15) >> 3) * 8 + (lane & 7);
                const uint32_t bd = sB + (uint32_t)(krow * 72 + n0) * 2;
                uint32_t bh[2], bl[2];
                ldm_x2t(bh, bd);
                ldm_x2t(bl, bd + 4608);
#pragma unroll
                for (int mf = 0; mf < 4; mf++) {
                    mma16816(acc[mf][nf], al[mf], bh);
                    mma16816(acc[mf][nf], ah[mf], bl);
                    mma16816(acc[mf][nf], ah[mf], bh);
                }
            }
        }
        __syncthreads();
        p ^= 1;
    }
}

// ---------------- kernels ----------------
__global__ void __launch_bounds__(256) k_split(const float* __restrict__ s,
                                               __half* __restrict__ dh,
                                               __half* __restrict__ dl, int n4)
{
    int i = blockIdx.x * 256 + threadIdx.x;
    if (i >= n4) return;
    float4 v = ((const float4*)s)[i];
    __half h0, h1, h2, h3, l0, l1, l2, l3;
    splitf(v.x, h0, l0); splitf(v.y, h1, l1); splitf(v.z, h2, l2); splitf(v.w, h3, l3);
    ((__half2*)dh)[i * 2]     = __halves2half2(h0, h1);
    ((__half2*)dh)[i * 2 + 1] = __halves2half2(h2, h3);
    ((__half2*)dl)[i * 2]     = __halves2half2(l0, l1);
    ((__half2*)dl)[i * 2 + 1] = __halves2half2(l2, l3);
}

// qkv; Q columns pre-scaled by ATT_SCALE
__global__ void __launch_bounds__(256, 2) k_qkv()
{
    const int row0 = blockIdx.y * 128, col0 = blockIdx.x * 128;
    float acc[4][4][4] = {};
    gemm_nt(g_xh + (size_t)row0 * DIMC, g_xl + (size_t)row0 * DIMC, DIMC,
            g_wqh + (size_t)col0 * DIMC, g_wql + (size_t)col0 * DIMC, DIMC,
            DIMC, acc);
    const int lane = threadIdx.x & 31, wid = threadIdx.x >> 5;
    const int wm = wid >> 2, wn = wid & 3, g = lane >> 2, tig = lane & 3;
    const float qs = (col0 < DIMC) ? ATT_SCALE : 1.f;   // whole 128-col tile within Q or not
#pragma unroll
    for (int mf = 0; mf < 4; mf++) {
        const int row = row0 + wm * 64 + mf * 16 + g;
#pragma unroll
        for (int nf = 0; nf < 4; nf++) {
            const int col = col0 + wn * 32 + nf * 8 + tig * 2;
            __half h0, h1, l0, l1;
            splitf(acc[mf][nf][0] * qs, h0, l0); splitf(acc[mf][nf][1] * qs, h1, l1);
            *(__half2*)&g_qkvh[(size_t)row * LDQKV + col] = __halves2half2(h0, h1);
            *(__half2*)&g_qkvl[(size_t)row * LDQKV + col] = __halves2half2(l0, l1);
            splitf(acc[mf][nf][2] * qs, h0, l0); splitf(acc[mf][nf][3] * qs, h1, l1);
            *(__half2*)&g_qkvh[(size_t)(row + 8) * LDQKV + col] = __halves2half2(h0, h1);
            *(__half2*)&g_qkvl[(size_t)(row + 8) * LDQKV + col] = __halves2half2(l0, l1);
        }
    }
}

__global__ void __launch_bounds__(256, 2) k_scores()
{
    const int z = blockIdx.z, b = z / HEADS, h = z % HEADS;
    const int row0 = blockIdx.y * 128, col0 = blockIdx.x * 128;
    const size_t qo = (size_t)b * NN * LDQKV + h * HD;
    float acc[4][4][4] = {};
    gemm_nt(g_qkvh + qo + (size_t)row0 * LDQKV, g_qkvl + qo + (size_t)row0 * LDQKV, LDQKV,
            g_qkvh + qo + DIMC + (size_t)col0 * LDQKV, g_qkvl + qo + DIMC + (size_t)col0 * LDQKV, LDQKV,
            HD, acc);
    const int lane = threadIdx.x & 31, wid = threadIdx.x >> 5;
    const int wm = wid >> 2, wn = wid & 3, g = lane >> 2, tig = lane & 3;
    float* S = g_S + (size_t)z * NN * NN;
#pragma unroll
    for (int mf = 0; mf < 4; mf++) {
        const int row = row0 + wm * 64 + mf * 16 + g;
#pragma unroll
        for (int nf = 0; nf < 4; nf++) {
            const int col = col0 + wn * 32 + nf * 8 + tig * 2;
            *(float2*)&S[(size_t)row * NN + col] = make_float2(acc[mf][nf][0], acc[mf][nf][1]);
            *(float2*)&S[(size_t)(row + 8) * NN + col] = make_float2(acc[mf][nf][2], acc[mf][nf][3]);
        }
    }
}

__global__ void __launch_bounds__(256, 3) k_av()
{
    const int z = blockIdx.z, b = z / HEADS, h = z % HEADS;
    const int row0 = blockIdx.y * 128;
    const size_t ao = (size_t)z * NN * NN + (size_t)row0 * NN;
    const size_t vo = (size_t)b * NN * LDQKV + 2 * DIMC + h * HD;
    float acc[4][2][4] = {};
    gemm_nn(g_Ah + ao, g_Al + ao, NN, g_qkvh + vo, g_qkvl + vo, LDQKV, NN, acc);
    const int lane = threadIdx.x & 31, wid = threadIdx.x >> 5;
    const int wm = wid >> 2, wn = wid & 3, g = lane >> 2, tig = lane & 3;
    __half* Avh = g_Avh + (size_t)z * NN * HD;
    __half* Avl = g_Avl + (size_t)z * NN * HD;
#pragma unroll
    for (int mf = 0; mf < 4; mf++) {
        const int row = row0 + wm * 64 + mf * 16 + g;
#pragma unroll
        for (int nf = 0; nf < 2; nf++) {
            const int col = wn * 16 + nf * 8 + tig * 2;
            __half h0, h1, l0, l1;
            splitf(acc[mf][nf][0], h0, l0); splitf(acc[mf][nf][1], h1, l1);
            *(__half2*)&Avh[(size_t)row * HD + col] = __halves2half2(h0, h1);
            *(__half2*)&Avl[(size_t)row * HD + col] = __halves2half2(l0, l1);
            splitf(acc[mf][nf][2], h0, l0); splitf(acc[mf][nf][3], h1, l1);
            *(__half2*)&Avh[(size_t)(row + 8) * HD + col] = __halves2half2(h0, h1);
            *(__half2*)&Avl[(size_t)(row + 8) * HD + col] = __halves2half2(l0, l1);
        }
    }
}

__global__ void __launch_bounds__(256, 3) k_aav(const float* __restrict__ lamb)
{
    const int z = blockIdx.z, b = z / HEADS, h = z % HEADS;
    const int row0 = blockIdx.y * 128;
    const size_t ao = (size_t)z * NN * NN + (size_t)row0 * NN;
    const size_t avo = (size_t)z * NN * HD;
    float acc[4][2][4] = {};
    gemm_nn(g_Ah + ao, g_Al + ao, NN, g_Avh + avo, g_Avl + avo, HD, NN, acc);
    const float lam = lamb[h];
    const float c1 = 1.f - 2.f * lam, c3 = 3.f * lam;
    const int lane = threadIdx.x & 31, wid = threadIdx.x >> 5;
    const int wm = wid >> 2, wn = wid & 3, g = lane >> 2, tig = lane & 3;
#pragma unroll
    for (int mf = 0; mf < 4; mf++) {
#pragma unroll
        for (int nf = 0; nf < 2; nf++) {
            const int col = wn * 16 + nf * 8 + tig * 2;
#pragma unroll
            for (int half_ = 0; half_ < 2; half_++) {
                const int row = row0 + wm * 64 + mf * 16 + g + half_ * 8;
                __half2 avh = *(const __half2*)&g_Avh[avo + (size_t)row * HD + col];
                __half2 avl = *(const __half2*)&g_Avl[avo + (size_t)row * HD + col];
                float av0 = __half2float(avh.x) + __half2float(avl.x);
                float av1 = __half2float(avh.y) + __half2float(avl.y);
                float o0 = fmaf(c3, acc[mf][nf][half_ * 2],     c1 * av0);
                float o1 = fmaf(c3, acc[mf][nf][half_ * 2 + 1], c1 * av1);
                __half h0, h1, l0, l1;
                splitf(o0, h0, l0); splitf(o1, h1, l1);
                const size_t oi = ((size_t)b * NN + row) * DIMC + h * HD + col;
                *(__half2*)&g_Oh[oi] = __halves2half2(h0, h1);
                *(__half2*)&g_Ol[oi] = __halves2half2(l0, l1);
            }
        }
    }
}

__global__ void __launch_bounds__(256, 2) k_out(const float* __restrict__ bias,
                                                float* __restrict__ out)
{
    const int row0 = blockIdx.y * 128, col0 = blockIdx.x * 128;
    float acc[4][4][4] = {};
    gemm_nt(g_Oh + (size_t)row0 * DIMC, g_Ol + (size_t)row0 * DIMC, DIMC,
            g_woh + (size_t)col0 * DIMC, g_wol + (size_t)col0 * DIMC, DIMC,
            DIMC, acc);
    const int lane = threadIdx.x & 31, wid = threadIdx.x >> 5;
    const int wm = wid >> 2, wn = wid & 3, g = lane >> 2, tig = lane & 3;
#pragma unroll
    for (int mf = 0; mf < 4; mf++) {
        const int row = row0 + wm * 64 + mf * 16 + g;
#pragma unroll
        for (int nf = 0; nf < 4; nf++) {
            const int col = col0 + wn * 32 + nf * 8 + tig * 2;
            const float b0 = bias[col], b1 = bias[col + 1];
            *(float2*)&out[(size_t)row * DIMC + col] =
                make_float2(acc[mf][nf][0] + b0, acc[mf][nf][1] + b1);
            *(float2*)&out[(size_t)(row + 8) * DIMC + col] =
                make_float2(acc[mf][nf][2] + b0, acc[mf][nf][3] + b1);
        }
    }
}

// Fused: L-mix -> softmax -> W-mix. Vectorized: float4 loads, 2-col processing, half2 stores.
__global__ void __launch_bounds__(256) k_mix(const float* __restrict__ Lw,
                                             const float* __restrict__ Lb,
                                             const float* __restrict__ Ww,
                                             const float* __restrict__ Wb)
{
    extern __shared__ float sm[];  // [12][1024]
    __shared__ float sL[144], sW[144], sbl[12], sbw[12];
    __shared__ float red[12][8];
    __shared__ float gmax[12], ginv[12];

    const int tid = threadIdx.x;
    const int b = blockIdx.x >> 10;
    const int n = blockIdx.x & 1023;

    if (tid < 144) { sL[tid] = Lw[tid]; sW[tid] = Ww[tid]; }
    if (tid < 12)  { sbl[tid] = Lb[tid]; sbw[tid] = Wb[tid]; }

    const float* Sbase = g_S + (size_t)b * HEADS * NN * NN + (size_t)n * NN;

    for (int idx = tid; idx < HEADS * (NN / 4); idx += 256) {
        const int h = idx >> 8, m4 = idx & 255;
        ((float4*)sm)[(h << 8) + m4] = *(const float4*)&Sbase[(size_t)h * NN * NN + m4 * 4];
    }
    __syncthreads();

    float lred[12];
#pragma unroll
    for (int g = 0; g < 12; g++) lred[g] = -1e30f;
    for (int m = tid * 2; m < NN; m += 512) {
        float2 s[12];
#pragma unroll
        for (int h = 0; h < 12; h++) s[h] = *(const float2*)&sm[(h << 10) + m];
#pragma unroll
        for (int g = 0; g < 12; g++) {
            float t0 = sbl[g], t1 = sbl[g];
#pragma unroll
            for (int h = 0; h < 12; h++) {
                t0 = fmaf(sL[g * 12 + h], s[h].x, t0);
                t1 = fmaf(sL[g * 12 + h], s[h].y, t1);
            }
            *(float2*)&sm[(g << 10) + m] = make_float2(t0, t1);
            lred[g] = fmaxf(lred[g], fmaxf(t0, t1));
        }
    }
    const int lane = tid & 31, wrp = tid >> 5;
#pragma unroll
    for (int g = 0; g < 12; g++) {
        float v = lred[g];
#pragma unroll
        for (int o = 16; o; o >>= 1) v = fmaxf(v, __shfl_xor_sync(0xffffffffu, v, o));
        if (lane == 0) red[g][wrp] = v;
    }
    __syncthreads();
    if (tid < 12) {
        float v = red[tid][0];
#pragma unroll
        for (int w = 1; w < 8; w++) v = fmaxf(v, red[tid][w]);
        gmax[tid] = v;
    }
    __syncthreads();

#pragma unroll
    for (int g = 0; g < 12; g++) lred[g] = 0.f;
    for (int m = tid * 2; m < NN; m += 512) {
#pragma unroll
        for (int g = 0; g < 12; g++) {
            float2 v = *(const float2*)&sm[(g << 10) + m];
            float e0 = __expf(v.x - gmax[g]);
            float e1 = __expf(v.y - gmax[g]);
            *(float2*)&sm[(g << 10) + m] = make_float2(e0, e1);
            lred[g] += e0 + e1;
        }
    }
#pragma unroll
    for (int g = 0; g < 12; g++) {
        float v = lred[g];
#pragma unroll
        for (int o = 16; o; o >>= 1) v += __shfl_xor_sync(0xffffffffu, v, o);
        if (lane == 0) red[g][wrp] = v;
    }
    __syncthreads();
    if (tid < 12) {
        float v = red[tid][0];
#pragma unroll
        for (int w = 1; w < 8; w++) v += red[tid][w];
        ginv[tid] = 1.f / v;
    }
    __syncthreads();

    const size_t abase = (size_t)b * HEADS * NN * NN + (size_t)n * NN;
    for (int m = tid * 2; m < NN; m += 512) {
        float2 p[12];
#pragma unroll
        for (int h = 0; h < 12; h++) {
            float2 v = *(const float2*)&sm[(h << 10) + m];
            p[h] = make_float2(v.x * ginv[h], v.y * ginv[h]);
        }
#pragma unroll
        for (int g = 0; g < 12; g++) {
            float a0 = sbw[g], a1 = sbw[g];
#pragma unroll
            for (int h = 0; h < 12; h++) {
                a0 = fmaf(sW[g * 12 + h], p[h].x, a0);
                a1 = fmaf(sW[g * 12 + h], p[h].y, a1);
            }
            __half h0, l0, h1, l1;
            splitf(a0, h0, l0); splitf(a1, h1, l1);
            *(__half2*)&g_Ah[abase + (size_t)g * NN * NN + m] = __halves2half2(h0, h1);
            *(__half2*)&g_Al[abase + (size_t)g * NN * NN + m] = __halves2half2(l0, l1);
        }
    }
}

// ---------------- launch ----------------
extern "C" void kernel_launch(void* const* d_in, const int* in_sizes, int n_in,
                              void* d_out, int out_size)
{
    (void)in_sizes; (void)n_in; (void)out_size;
    const float* x      = (const float*)d_in[0];
    const float* qkv_w  = (const float*)d_in[1];
    const float* Lw     = (const float*)d_in[2];
    const float* Lb     = (const float*)d_in[3];
    const float* Ww     = (const float*)d_in[4];
    const float* Wb     = (const float*)d_in[5];
    const float* lamb   = (const float*)d_in[6];
    const float* Wout   = (const float*)d_in[7];
    const float* bout   = (const float*)d_in[8];
    float* out = (float*)d_out;

    const int NT_SMEM = 98304, NN_SMEM = 59392, MIX_SMEM = HEADS * NN * (int)sizeof(float);
    cudaFuncSetAttribute(k_qkv,    cudaFuncAttributeMaxDynamicSharedMemorySize, NT_SMEM);
    cudaFuncSetAttribute(k_scores, cudaFuncAttributeMaxDynamicSharedMemorySize, NT_SMEM);
    cudaFuncSetAttribute(k_out,    cudaFuncAttributeMaxDynamicSharedMemorySize, NT_SMEM);
    cudaFuncSetAttribute(k_av,     cudaFuncAttributeMaxDynamicSharedMemorySize, NN_SMEM);
    cudaFuncSetAttribute(k_aav,    cudaFuncAttributeMaxDynamicSharedMemorySize, NN_SMEM);
    cudaFuncSetAttribute(k_mix,    cudaFuncAttributeMaxDynamicSharedMemorySize, MIX_SMEM);

    __half *xh, *xl, *wqh, *wql, *woh, *wol;
    cudaGetSymbolAddress((void**)&xh,  g_xh);  cudaGetSymbolAddress((void**)&xl,  g_xl);
    cudaGetSymbolAddress((void**)&wqh, g_wqh); cudaGetSymbolAddress((void**)&wql, g_wql);
    cudaGetSymbolAddress((void**)&woh, g_woh); cudaGetSymbolAddress((void**)&wol, g_wol);

    {
        int n4 = NB * NN * DIMC / 4;
        k_split<<<(n4 + 255) / 256, 256>>>(x, xh, xl, n4);
        n4 = 3 * DIMC * DIMC / 4;
        k_split<<<(n4 + 255) / 256, 256>>>(qkv_w, wqh, wql, n4);
        n4 = DIMC * DIMC / 4;
        k_split<<<(n4 + 255) / 256, 256>>>(Wout, woh, wol, n4);
    }
    k_qkv<<<dim3(LDQKV / 128, (NB * NN) / 128), 256, NT_SMEM>>>();
    k_scores<<<dim3(NN / 128, NN / 128, NB * HEADS), 256, NT_SMEM>>>();
    k_mix<<<NB * NN, 256, MIX_SMEM>>>(Lw, Lb, Ww, Wb);
    k_av<<<dim3(1, NN / 128, NB * HEADS), 256, NN_SMEM>>>();
    k_aav<<<dim3(1, NN / 128, NB * HEADS), 256, NN_SMEM>>>(lamb);
    k_out<<<dim3(DIMC / 128, (NB * NN) / 128), 256, NT_SMEM>>>(bout, out);
}

// round 8
// speedup vs baseline: 1.9973x; 1.0581x over previous
#include <cuda_runtime.h>
#include <cuda_fp16.h>
#include <stdint.h>

#define HEADS 12
#define HD 64
#define DIMC 768
#define NB 4
#define NN 1024
#define LDQKV (3 * DIMC)
#define ATT_SCALE 0.125f

// ---------------- global scratch ----------------
// int8 hi/lo planes + per-row scales for the qkv GEMM operands
__device__ int8_t g_xih[(size_t)NB * NN * DIMC], g_xil[(size_t)NB * NN * DIMC];
__device__ float  g_xs[NB * NN];
__device__ int8_t g_wih[(size_t)3 * DIMC * DIMC], g_wil[(size_t)3 * DIMC * DIMC];
__device__ float  g_ws[3 * DIMC];
// fp16 hi/lo planes (unchanged downstream pipeline)
__device__ __half g_woh[(size_t)DIMC * DIMC],     g_wol[(size_t)DIMC * DIMC];
__device__ __half g_qkvh[(size_t)NB * NN * LDQKV], g_qkvl[(size_t)NB * NN * LDQKV];
__device__ float  g_S[(size_t)NB * HEADS * NN * NN];
__device__ __half g_Ah[(size_t)NB * HEADS * NN * NN], g_Al[(size_t)NB * HEADS * NN * NN];
__device__ __half g_Avh[(size_t)NB * HEADS * NN * HD], g_Avl[(size_t)NB * HEADS * NN * HD];
__device__ __half g_Oh[(size_t)NB * NN * DIMC],   g_Ol[(size_t)NB * NN * DIMC];

// ---------------- helpers ----------------
__device__ __forceinline__ void splitf(float v, __half &h, __half &l) {
    h = __float2half_rn(v);
    l = __float2half_rn(v - __half2float(h));
}
__device__ __forceinline__ void mma16816(float *c, const uint32_t *a, const uint32_t *b) {
    asm volatile(
        "mma.sync.aligned.m16n8k16.row.col.f32.f16.f16.f32 "
        "{%0,%1,%2,%3},{%4,%5,%6,%7},{%8,%9},{%0,%1,%2,%3};"
        : "+f"(c[0]), "+f"(c[1]), "+f"(c[2]), "+f"(c[3])
        : "r"(a[0]), "r"(a[1]), "r"(a[2]), "r"(a[3]), "r"(b[0]), "r"(b[1]));
}
__device__ __forceinline__ void imma16832(int *c, const uint32_t *a, const uint32_t *b) {
    asm volatile(
        "mma.sync.aligned.m16n8k32.row.col.s32.s8.s8.s32 "
        "{%0,%1,%2,%3},{%4,%5,%6,%7},{%8,%9},{%0,%1,%2,%3};"
        : "+r"(c[0]), "+r"(c[1]), "+r"(c[2]), "+r"(c[3])
        : "r"(a[0]), "r"(a[1]), "r"(a[2]), "r"(a[3]), "r"(b[0]), "r"(b[1]));
}
__device__ __forceinline__ void ldm_x4(uint32_t (&r)[4], uint32_t a) {
    asm volatile("ldmatrix.sync.aligned.m8n8.x4.shared.b16 {%0,%1,%2,%3}, [%4];"
                 : "=r"(r[0]), "=r"(r[1]), "=r"(r[2]), "=r"(r[3]) : "r"(a));
}
__device__ __forceinline__ void ldm_x2(uint32_t (&r)[2], uint32_t a) {
    asm volatile("ldmatrix.sync.aligned.m8n8.x2.shared.b16 {%0,%1}, [%2];"
                 : "=r"(r[0]), "=r"(r[1]) : "r"(a));
}
__device__ __forceinline__ void ldm_x2t(uint32_t (&r)[2], uint32_t a) {
    asm volatile("ldmatrix.sync.aligned.m8n8.x2.trans.shared.b16 {%0,%1}, [%2];"
                 : "=r"(r[0]), "=r"(r[1]) : "r"(a));
}
__device__ __forceinline__ void cpa16(uint32_t s, const void *g) {
    asm volatile("cp.async.cg.shared.global [%0], [%1], 16;" :: "r"(s), "l"(g));
}
__device__ __forceinline__ void cpa_commit() { asm volatile("cp.async.commit_group;"); }

// ================= fp16 NT engine (R7-proven): BM=128, BN=128, BK=16, 4-stage =================
__device__ __forceinline__ void gemm_nt(
    const __half* Agh, const __half* Agl, int lda,
    const __half* Bgh, const __half* Bgl, int ldb,
    int K, float (&acc)[4][4][4])
{
    extern __shared__ __align__(16) __half smx[];
    const uint32_t sb = (uint32_t)__cvta_generic_to_shared(smx);
    const int t = threadIdx.x, lane = t & 31, wid = t >> 5;
    const int wm = wid >> 2, wn = wid & 3;
    const int r = t >> 1, s16 = t & 1;

    const __half* pAh = Agh + (size_t)r * lda + s16 * 8;
    const __half* pAl = Agl + (size_t)r * lda + s16 * 8;
    const __half* pBh = Bgh + (size_t)r * ldb + s16 * 8;
    const __half* pBl = Bgl + (size_t)r * ldb + s16 * 8;
    const uint32_t soff = (uint32_t)(r * 48 + s16 * 16);

    const int nst = K >> 4;
    auto issue = [&](int i) {
        const uint32_t s0 = sb + (uint32_t)(i & 3) * 24576 + soff;
        const int k0 = i * 16;
        cpa16(s0,         pAh + k0);
        cpa16(s0 + 6144,  pAl + k0);
        cpa16(s0 + 12288, pBh + k0);
        cpa16(s0 + 18432, pBl + k0);
        cpa_commit();
    };

    issue(0);
    if (nst > 1) issue(1);
    if (nst > 2) issue(2);

    for (int i = 0; i < nst; i++) {
        if (i + 3 < nst) {
            issue(i + 3);
            asm volatile("cp.async.wait_group 3;");
        } else {
            const int rem = nst - 1 - i;
            if (rem == 2)      asm volatile("cp.async.wait_group 2;");
            else if (rem == 1) asm volatile("cp.async.wait_group 1;");
            else               asm volatile("cp.async.wait_group 0;");
        }
        __syncthreads();
        const uint32_t sA = sb + (uint32_t)(i & 3) * 24576;
        const uint32_t sB = sA + 12288;
        uint32_t ah[4][4], al[4][4];
#pragma unroll
        for (int mf = 0; mf < 4; mf++) {
            const int m0 = wm * 64 + mf * 16;
            const uint32_t ad = sA + (uint32_t)((m0 + (lane & 15)) * 48) + ((lane >> 4) & 1) * 16;
            ldm_x4(ah[mf], ad);
            ldm_x4(al[mf], ad + 6144);
        }
#pragma unroll
        for (int nf = 0; nf < 4; nf++) {
            const int n0 = wn * 32 + nf * 8;
            const uint32_t bd = sB + (uint32_t)((n0 + (lane & 7)) * 48) + (((lane & 15) >> 3) & 1) * 16;
            uint32_t bh[2], bl[2];
            ldm_x2(bh, bd);
            ldm_x2(bl, bd + 6144);
#pragma unroll
            for (int mf = 0; mf < 4; mf++) {
                mma16816(acc[mf][nf], al[mf], bh);
                mma16816(acc[mf][nf], ah[mf], bl);
                mma16816(acc[mf][nf], ah[mf], bh);
            }
        }
        __syncthreads();
    }
}

// ================= fp16 NN engine (R4-proven): BM=128, BN=64, BK=32, 2-stage =================
__device__ __forceinline__ void gemm_nn(
    const __half* Agh, const __half* Agl, int lda,
    const __half* Bgh, const __half* Bgl, int ldb,
    int K, float (&acc)[4][2][4])
{
    extern __shared__ __align__(16) __half smx[];
    const uint32_t sb = (uint32_t)__cvta_generic_to_shared(smx);
    const int t = threadIdx.x, lane = t & 31, wid = t >> 5;
    const int wm = wid >> 2, wn = wid & 3;
    const int r = t >> 1, ch = (t & 1) * 2;
    const int kr = t >> 3, nch = t & 7;

    const __half* pAh = Agh + (size_t)r * lda + ch * 8;
    const __half* pAl = Agl + (size_t)r * lda + ch * 8;
    const __half* pBh = Bgh + (size_t)kr * ldb + nch * 8;
    const __half* pBl = Bgl + (size_t)kr * ldb + nch * 8;
    const uint32_t aoff = (uint32_t)(r * 40 + ch * 8) * 2;
    const uint32_t boff = (uint32_t)(kr * 72 + nch * 8) * 2;

    const int nst = K / 32;
    auto issue = [&](int st, int k0) {
        uint32_t s0 = sb + st * 29696;
        cpa16(s0 + aoff,              pAh + k0); cpa16(s0 + aoff + 16,         pAh + k0 + 8);
        cpa16(s0 + 10240 + aoff,      pAl + k0); cpa16(s0 + 10240 + aoff + 16, pAl + k0 + 8);
        cpa16(s0 + 20480 + boff, pBh + (size_t)k0 * ldb);
        cpa16(s0 + 25088 + boff, pBl + (size_t)k0 * ldb);
        cpa_commit();
    };

    issue(0, 0);
    int p = 0;
    for (int i = 0; i < nst; i++) {
        if (i + 1 < nst) { issue(p ^ 1, (i + 1) * 32); asm volatile("cp.async.wait_group 1;"); }
        else asm volatile("cp.async.wait_group 0;");
        __syncthreads();
        const uint32_t sA = sb + p * 29696;
        const uint32_t sB = sA + 20480;
#pragma unroll
        for (int s2 = 0; s2 < 2; s2++) {
            uint32_t ah[4][4], al[4][4];
#pragma unroll
            for (int mf = 0; mf < 4; mf++) {
                const int m0 = wm * 64 + mf * 16;
                const uint32_t ad = sA + (uint32_t)((m0 + (lane & 15)) * 40) * 2
                                  + s2 * 32 + ((lane >> 4) & 1) * 16;
                ldm_x4(ah[mf], ad);
                ldm_x4(al[mf], ad + 10240);
            }
#pragma unroll
            for (int nf = 0; nf < 2; nf++) {
                const int n0 = wn * 16 + nf * 8;
                const int krow = s2 * 16 + ((lane & 15) >> 3) * 8 + (lane & 7);
                const uint32_t bd = sB + (uint32_t)(krow * 72 + n0) * 2;
                uint32_t bh[2], bl[2];
                ldm_x2t(bh, bd);
                ldm_x2t(bl, bd + 4608);
#pragma unroll
                for (int mf = 0; mf < 4; mf++) {
                    mma16816(acc[mf][nf], al[mf], bh);
                    mma16816(acc[mf][nf], ah[mf], bl);
                    mma16816(acc[mf][nf], ah[mf], bh);
                }
            }
        }
        __syncthreads();
        p ^= 1;
    }
}

// ---------------- quantization: x = s_row * (128*h + l), h,l int8 ----------------
__global__ void __launch_bounds__(256) k_quant(const float* __restrict__ s, int K,
                                               int8_t* __restrict__ dh,
                                               int8_t* __restrict__ dl,
                                               float* __restrict__ sc)
{
    const int row = blockIdx.x;
    const float* p = s + (size_t)row * K;
    __shared__ float red[8];
    float m = 0.f;
    for (int i = threadIdx.x; i < K; i += 256) m = fmaxf(m, fabsf(p[i]));
#pragma unroll
    for (int o = 16; o; o >>= 1) m = fmaxf(m, __shfl_xor_sync(0xffffffffu, m, o));
    if ((threadIdx.x & 31) == 0) red[threadIdx.x >> 5] = m;
    __syncthreads();
    if (threadIdx.x == 0) {
        float v = red[0];
#pragma unroll
        for (int w = 1; w < 8; w++) v = fmaxf(v, red[w]);
        red[0] = v;
        sc[row] = v * (1.f / 16256.f);
    }
    __syncthreads();
    const float mx = red[0];
    const float inv = mx > 0.f ? 16256.f / mx : 0.f;
    for (int i = threadIdx.x; i < K; i += 256) {
        float q = p[i] * inv;
        float hf = rintf(q * (1.f / 128.f));
        float lf = rintf(q - 128.f * hf);
        dh[(size_t)row * K + i] = (int8_t)hf;
        dl[(size_t)row * K + i] = (int8_t)lf;
    }
}

// ================= int8 NT engine for qkv: BM=128, BN=128, BK=32, 4-stage, 512 thr =================
// Warp grid 4x4, warp tile 32x32. Stage: Ah 0, Al 6144, Bh 12288, Bl 18432; stride 24576 (96KB total).
// Row = 32 int8 content, 48B stride (16B-aligned cp.async; conflict-free ldmatrix as in fp16 engine).
// s8 m16n8k32 fragments are byte-identical to fp16 m16n8k16 fragments -> reuse ldmatrix addressing.
__global__ void __launch_bounds__(512, 1) k_qkv_i8()
{
    extern __shared__ __align__(16) int8_t smi[];
    const uint32_t sb = (uint32_t)__cvta_generic_to_shared(smi);
    const int t = threadIdx.x, lane = t & 31, wid = t >> 5;
    const int wm = wid >> 2, wn = wid & 3;
    const int row0 = blockIdx.y * 128, col0 = blockIdx.x * 128;

    int hh[2][4][4] = {};
    int cx[2][4][4] = {};

    // loaders: 512 threads, 2 cp.async each (one A-plane seg, one B-plane seg)
    const int lrow = (t >> 1) & 127, lseg = t & 1, lps = t >> 8;   // lps: 0=hi planes, 1=lo planes
    const int8_t* pA = (lps ? g_xil : g_xih) + (size_t)(row0 + lrow) * DIMC + lseg * 16;
    const int8_t* pB = (lps ? g_wil : g_wih) + (size_t)(col0 + lrow) * DIMC + lseg * 16;
    const uint32_t aoff = (uint32_t)(lps * 6144 + lrow * 48 + lseg * 16);
    const uint32_t boff = 12288u + (uint32_t)(lps * 6144 + lrow * 48 + lseg * 16);

    const int nst = DIMC / 32;   // 24
    auto issue = [&](int i) {
        const uint32_t s0 = sb + (uint32_t)(i & 3) * 24576;
        cpa16(s0 + aoff, pA + i * 32);
        cpa16(s0 + boff, pB + i * 32);
        cpa_commit();
    };

    issue(0); issue(1); issue(2);

    for (int i = 0; i < nst; i++) {
        if (i + 3 < nst) {
            issue(i + 3);
            asm volatile("cp.async.wait_group 3;");
        } else {
            const int rem = nst - 1 - i;
            if (rem == 2)      asm volatile("cp.async.wait_group 2;");
            else if (rem == 1) asm volatile("cp.async.wait_group 1;");
            else               asm volatile("cp.async.wait_group 0;");
        }
        __syncthreads();
        const uint32_t sA = sb + (uint32_t)(i & 3) * 24576;
        const uint32_t sB = sA + 12288;
        uint32_t ah[2][4], al[2][4];
#pragma unroll
        for (int mf = 0; mf < 2; mf++) {
            const int m0 = wm * 32 + mf * 16;
            const uint32_t ad = sA + (uint32_t)((m0 + (lane & 15)) * 48) + ((lane >> 4) & 1) * 16;
            ldm_x4(ah[mf], ad);
            ldm_x4(al[mf], ad + 6144);
        }
#pragma unroll
        for (int nf = 0; nf < 4; nf++) {
            const int n0 = wn * 32 + nf * 8;
            const uint32_t bd = sB + (uint32_t)((n0 + (lane & 7)) * 48) + (((lane >> 3) & 1)) * 16;
            uint32_t bh[2], bl[2];
            ldm_x2(bh, bd);
            ldm_x2(bl, bd + 6144);
#pragma unroll
            for (int mf = 0; mf < 2; mf++) {
                imma16832(hh[mf][nf], ah[mf], bh);
                imma16832(cx[mf][nf], ah[mf], bl);
                imma16832(cx[mf][nf], al[mf], bh);
            }
        }
        __syncthreads();
    }

    // epilogue: combine, scale, fold ATT_SCALE for Q tiles, write fp16 hi/lo planes
    const int g = lane >> 2, tig = lane & 3;
    const float qs = (col0 < DIMC) ? ATT_SCALE : 1.f;
#pragma unroll
    for (int mf = 0; mf < 2; mf++) {
        const int row = row0 + wm * 32 + mf * 16 + g;
        const float sr0 = g_xs[row] * qs, sr1 = g_xs[row + 8] * qs;
#pragma unroll
        for (int nf = 0; nf < 4; nf++) {
            const int col = col0 + wn * 32 + nf * 8 + tig * 2;
            const float sc0 = g_ws[col], sc1 = g_ws[col + 1];
            const float v00 = sr0 * sc0 * (16384.f * (float)hh[mf][nf][0] + 128.f * (float)cx[mf][nf][0]);
            const float v01 = sr0 * sc1 * (16384.f * (float)hh[mf][nf][1] + 128.f * (float)cx[mf][nf][1]);
            const float v10 = sr1 * sc0 * (16384.f * (float)hh[mf][nf][2] + 128.f * (float)cx[mf][nf][2]);
            const float v11 = sr1 * sc1 * (16384.f * (float)hh[mf][nf][3] + 128.f * (float)cx[mf][nf][3]);
            __half h0, h1, l0, l1;
            splitf(v00, h0, l0); splitf(v01, h1, l1);
            *(__half2*)&g_qkvh[(size_t)row * LDQKV + col] = __halves2half2(h0, h1);
            *(__half2*)&g_qkvl[(size_t)row * LDQKV + col] = __halves2half2(l0, l1);
            splitf(v10, h0, l0); splitf(v11, h1, l1);
            *(__half2*)&g_qkvh[(size_t)(row + 8) * LDQKV + col] = __halves2half2(h0, h1);
            *(__half2*)&g_qkvl[(size_t)(row + 8) * LDQKV + col] = __halves2half2(l0, l1);
        }
    }
}

// ---------------- remaining kernels (R7-proven) ----------------
__global__ void __launch_bounds__(256) k_split(const float* __restrict__ s,
                                               __half* __restrict__ dh,
                                               __half* __restrict__ dl, int n4)
{
    int i = blockIdx.x * 256 + threadIdx.x;
    if (i >= n4) return;
    float4 v = ((const float4*)s)[i];
    __half h0, h1, h2, h3, l0, l1, l2, l3;
    splitf(v.x, h0, l0); splitf(v.y, h1, l1); splitf(v.z, h2, l2); splitf(v.w, h3, l3);
    ((__half2*)dh)[i * 2]     = __halves2half2(h0, h1);
    ((__half2*)dh)[i * 2 + 1] = __halves2half2(h2, h3);
    ((__half2*)dl)[i * 2]     = __halves2half2(l0, l1);
    ((__half2*)dl)[i * 2 + 1] = __halves2half2(l2, l3);
}

__global__ void __launch_bounds__(256, 2) k_scores()
{
    const int z = blockIdx.z, b = z / HEADS, h = z % HEADS;
    const int row0 = blockIdx.y * 128, col0 = blockIdx.x * 128;
    const size_t qo = (size_t)b * NN * LDQKV + h * HD;
    float acc[4][4][4] = {};
    gemm_nt(g_qkvh + qo + (size_t)row0 * LDQKV, g_qkvl + qo + (size_t)row0 * LDQKV, LDQKV,
            g_qkvh + qo + DIMC + (size_t)col0 * LDQKV, g_qkvl + qo + DIMC + (size_t)col0 * LDQKV, LDQKV,
            HD, acc);
    const int lane = threadIdx.x & 31, wid = threadIdx.x >> 5;
    const int wm = wid >> 2, wn = wid & 3, g = lane >> 2, tig = lane & 3;
    float* S = g_S + (size_t)z * NN * NN;
#pragma unroll
    for (int mf = 0; mf < 4; mf++) {
        const int row = row0 + wm * 64 + mf * 16 + g;
#pragma unroll
        for (int nf = 0; nf < 4; nf++) {
            const int col = col0 + wn * 32 + nf * 8 + tig * 2;
            *(float2*)&S[(size_t)row * NN + col] = make_float2(acc[mf][nf][0], acc[mf][nf][1]);
            *(float2*)&S[(size_t)(row + 8) * NN + col] = make_float2(acc[mf][nf][2], acc[mf][nf][3]);
        }
    }
}

__global__ void __launch_bounds__(256, 3) k_av()
{
    const int z = blockIdx.z, b = z / HEADS, h = z % HEADS;
    const int row0 = blockIdx.y * 128;
    const size_t ao = (size_t)z * NN * NN + (size_t)row0 * NN;
    const size_t vo = (size_t)b * NN * LDQKV + 2 * DIMC + h * HD;
    float acc[4][2][4] = {};
    gemm_nn(g_Ah + ao, g_Al + ao, NN, g_qkvh + vo, g_qkvl + vo, LDQKV, NN, acc);
    const int lane = threadIdx.x & 31, wid = threadIdx.x >> 5;
    const int wm = wid >> 2, wn = wid & 3, g = lane >> 2, tig = lane & 3;
    __half* Avh = g_Avh + (size_t)z * NN * HD;
    __half* Avl = g_Avl + (size_t)z * NN * HD;
#pragma unroll
    for (int mf = 0; mf < 4; mf++) {
        const int row = row0 + wm * 64 + mf * 16 + g;
#pragma unroll
        for (int nf = 0; nf < 2; nf++) {
            const int col = wn * 16 + nf * 8 + tig * 2;
            __half h0, h1, l0, l1;
            splitf(acc[mf][nf][0], h0, l0); splitf(acc[mf][nf][1], h1, l1);
            *(__half2*)&Avh[(size_t)row * HD + col] = __halves2half2(h0, h1);
            *(__half2*)&Avl[(size_t)row * HD + col] = __halves2half2(l0, l1);
            splitf(acc[mf][nf][2], h0, l0); splitf(acc[mf][nf][3], h1, l1);
            *(__half2*)&Avh[(size_t)(row + 8) * HD + col] = __halves2half2(h0, h1);
            *(__half2*)&Avl[(size_t)(row + 8) * HD + col] = __halves2half2(l0, l1);
        }
    }
}

__global__ void __launch_bounds__(256, 3) k_aav(const float* __restrict__ lamb)
{
    const int z = blockIdx.z, b = z / HEADS, h = z % HEADS;
    const int row0 = blockIdx.y * 128;
    const size_t ao = (size_t)z * NN * NN + (size_t)row0 * NN;
    const size_t avo = (size_t)z * NN * HD;
    float acc[4][2][4] = {};
    gemm_nn(g_Ah + ao, g_Al + ao, NN, g_Avh + avo, g_Avl + avo, HD, NN, acc);
    const float lam = lamb[h];
    const float c1 = 1.f - 2.f * lam, c3 = 3.f * lam;
    const int lane = threadIdx.x & 31, wid = threadIdx.x >> 5;
    const int wm = wid >> 2, wn = wid & 3, g = lane >> 2, tig = lane & 3;
#pragma unroll
    for (int mf = 0; mf < 4; mf++) {
#pragma unroll
        for (int nf = 0; nf < 2; nf++) {
            const int col = wn * 16 + nf * 8 + tig * 2;
#pragma unroll
            for (int half_ = 0; half_ < 2; half_++) {
                const int row = row0 + wm * 64 + mf * 16 + g + half_ * 8;
                __half2 avh = *(const __half2*)&g_Avh[avo + (size_t)row * HD + col];
                __half2 avl = *(const __half2*)&g_Avl[avo + (size_t)row * HD + col];
                float av0 = __half2float(avh.x) + __half2float(avl.x);
                float av1 = __half2float(avh.y) + __half2float(avl.y);
                float o0 = fmaf(c3, acc[mf][nf][half_ * 2],     c1 * av0);
                float o1 = fmaf(c3, acc[mf][nf][half_ * 2 + 1], c1 * av1);
                __half h0, h1, l0, l1;
                splitf(o0, h0, l0); splitf(o1, h1, l1);
                const size_t oi = ((size_t)b * NN + row) * DIMC + h * HD + col;
                *(__half2*)&g_Oh[oi] = __halves2half2(h0, h1);
                *(__half2*)&g_Ol[oi] = __halves2half2(l0, l1);
            }
        }
    }
}

__global__ void __launch_bounds__(256, 2) k_out(const float* __restrict__ bias,
                                                float* __restrict__ out)
{
    const int row0 = blockIdx.y * 128, col0 = blockIdx.x * 128;
    float acc[4][4][4] = {};
    gemm_nt(g_Oh + (size_t)row0 * DIMC, g_Ol + (size_t)row0 * DIMC, DIMC,
            g_woh + (size_t)col0 * DIMC, g_wol + (size_t)col0 * DIMC, DIMC,
            DIMC, acc);
    const int lane = threadIdx.x & 31, wid = threadIdx.x >> 5;
    const int wm = wid >> 2, wn = wid & 3, g = lane >> 2, tig = lane & 3;
#pragma unroll
    for (int mf = 0; mf < 4; mf++) {
        const int row = row0 + wm * 64 + mf * 16 + g;
#pragma unroll
        for (int nf = 0; nf < 4; nf++) {
            const int col = col0 + wn * 32 + nf * 8 + tig * 2;
            const float b0 = bias[col], b1 = bias[col + 1];
            *(float2*)&out[(size_t)row * DIMC + col] =
                make_float2(acc[mf][nf][0] + b0, acc[mf][nf][1] + b1);
            *(float2*)&out[(size_t)(row + 8) * DIMC + col] =
                make_float2(acc[mf][nf][2] + b0, acc[mf][nf][3] + b1);
        }
    }
}

__global__ void __launch_bounds__(256) k_mix(const float* __restrict__ Lw,
                                             const float* __restrict__ Lb,
                                             const float* __restrict__ Ww,
                                             const float* __restrict__ Wb)
{
    extern __shared__ float sm[];  // [12][1024]
    __shared__ float sL[144], sW[144], sbl[12], sbw[12];
    __shared__ float red[12][8];
    __shared__ float gmax[12], ginv[12];

    const int tid = threadIdx.x;
    const int b = blockIdx.x >> 10;
    const int n = blockIdx.x & 1023;

    if (tid < 144) { sL[tid] = Lw[tid]; sW[tid] = Ww[tid]; }
    if (tid < 12)  { sbl[tid] = Lb[tid]; sbw[tid] = Wb[tid]; }

    const float* Sbase = g_S + (size_t)b * HEADS * NN * NN + (size_t)n * NN;

    for (int idx = tid; idx < HEADS * (NN / 4); idx += 256) {
        const int h = idx >> 8, m4 = idx & 255;
        ((float4*)sm)[(h << 8) + m4] = *(const float4*)&Sbase[(size_t)h * NN * NN + m4 * 4];
    }
    __syncthreads();

    float lred[12];
#pragma unroll
    for (int g = 0; g < 12; g++) lred[g] = -1e30f;
    for (int m = tid * 2; m < NN; m += 512) {
        float2 s[12];
#pragma unroll
        for (int h = 0; h < 12; h++) s[h] = *(const float2*)&sm[(h << 10) + m];
#pragma unroll
        for (int g = 0; g < 12; g++) {
            float t0 = sbl[g], t1 = sbl[g];
#pragma unroll
            for (int h = 0; h < 12; h++) {
                t0 = fmaf(sL[g * 12 + h], s[h].x, t0);
                t1 = fmaf(sL[g * 12 + h], s[h].y, t1);
            }
            *(float2*)&sm[(g << 10) + m] = make_float2(t0, t1);
            lred[g] = fmaxf(lred[g], fmaxf(t0, t1));
        }
    }
    const int lane = tid & 31, wrp = tid >> 5;
#pragma unroll
    for (int g = 0; g < 12; g++) {
        float v = lred[g];
#pragma unroll
        for (int o = 16; o; o >>= 1) v = fmaxf(v, __shfl_xor_sync(0xffffffffu, v, o));
        if (lane == 0) red[g][wrp] = v;
    }
    __syncthreads();
    if (tid < 12) {
        float v = red[tid][0];
#pragma unroll
        for (int w = 1; w < 8; w++) v = fmaxf(v, red[tid][w]);
        gmax[tid] = v;
    }
    __syncthreads();

#pragma unroll
    for (int g = 0; g < 12; g++) lred[g] = 0.f;
    for (int m = tid * 2; m < NN; m += 512) {
#pragma unroll
        for (int g = 0; g < 12; g++) {
            float2 v = *(const float2*)&sm[(g << 10) + m];
            float e0 = __expf(v.x - gmax[g]);
            float e1 = __expf(v.y - gmax[g]);
            *(float2*)&sm[(g << 10) + m] = make_float2(e0, e1);
            lred[g] += e0 + e1;
        }
    }
#pragma unroll
    for (int g = 0; g < 12; g++) {
        float v = lred[g];
#pragma unroll
        for (int o = 16; o; o >>= 1) v += __shfl_xor_sync(0xffffffffu, v, o);
        if (lane == 0) red[g][wrp] = v;
    }
    __syncthreads();
    if (tid < 12) {
        float v = red[tid][0];
#pragma unroll
        for (int w = 1; w < 8; w++) v += red[tid][w];
        ginv[tid] = 1.f / v;
    }
    __syncthreads();

    const size_t abase = (size_t)b * HEADS * NN * NN + (size_t)n * NN;
    for (int m = tid * 2; m < NN; m += 512) {
        float2 p[12];
#pragma unroll
        for (int h = 0; h < 12; h++) {
            float2 v = *(const float2*)&sm[(h << 10) + m];
            p[h] = make_float2(v.x * ginv[h], v.y * ginv[h]);
        }
#pragma unroll
        for (int g = 0; g < 12; g++) {
            float a0 = sbw[g], a1 = sbw[g];
#pragma unroll
            for (int h = 0; h < 12; h++) {
                a0 = fmaf(sW[g * 12 + h], p[h].x, a0);
                a1 = fmaf(sW[g * 12 + h], p[h].y, a1);
            }
            __half h0, l0, h1, l1;
            splitf(a0, h0, l0); splitf(a1, h1, l1);
            *(__half2*)&g_Ah[abase + (size_t)g * NN * NN + m] = __halves2half2(h0, h1);
            *(__half2*)&g_Al[abase + (size_t)g * NN * NN + m] = __halves2half2(l0, l1);
        }
    }
}

// ---------------- launch ----------------
extern "C" void kernel_launch(void* const* d_in, const int* in_sizes, int n_in,
                              void* d_out, int out_size)
{
    (void)in_sizes; (void)n_in; (void)out_size;
    const float* x      = (const float*)d_in[0];
    const float* qkv_w  = (const float*)d_in[1];
    const float* Lw     = (const float*)d_in[2];
    const float* Lb     = (const float*)d_in[3];
    const float* Ww     = (const float*)d_in[4];
    const float* Wb     = (const float*)d_in[5];
    const float* lamb   = (const float*)d_in[6];
    const float* Wout   = (const float*)d_in[7];
    const float* bout   = (const float*)d_in[8];
    float* out = (float*)d_out;

    const int NT_SMEM = 98304, NN_SMEM = 59392, I8_SMEM = 98304;
    const int MIX_SMEM = HEADS * NN * (int)sizeof(float);
    cudaFuncSetAttribute(k_qkv_i8, cudaFuncAttributeMaxDynamicSharedMemorySize, I8_SMEM);
    cudaFuncSetAttribute(k_scores, cudaFuncAttributeMaxDynamicSharedMemorySize, NT_SMEM);
    cudaFuncSetAttribute(k_out,    cudaFuncAttributeMaxDynamicSharedMemorySize, NT_SMEM);
    cudaFuncSetAttribute(k_av,     cudaFuncAttributeMaxDynamicSharedMemorySize, NN_SMEM);
    cudaFuncSetAttribute(k_aav,    cudaFuncAttributeMaxDynamicSharedMemorySize, NN_SMEM);
    cudaFuncSetAttribute(k_mix,    cudaFuncAttributeMaxDynamicSharedMemorySize, MIX_SMEM);

    int8_t *xih, *xil, *wih, *wil;
    float *xs, *ws;
    __half *woh, *wol;
    cudaGetSymbolAddress((void**)&xih, g_xih); cudaGetSymbolAddress((void**)&xil, g_xil);
    cudaGetSymbolAddress((void**)&xs,  g_xs);
    cudaGetSymbolAddress((void**)&wih, g_wih); cudaGetSymbolAddress((void**)&wil, g_wil);
    cudaGetSymbolAddress((void**)&ws,  g_ws);
    cudaGetSymbolAddress((void**)&woh, g_woh); cudaGetSymbolAddress((void**)&wol, g_wol);

    // 0) quantize x and qkv_w (int8 hi/lo + per-row scales); split Wout to fp16 planes
    k_quant<<<NB * NN, 256>>>(x, DIMC, xih, xil, xs);
    k_quant<<<3 * DIMC, 256>>>(qkv_w, DIMC, wih, wil, ws);
    {
        int n4 = DIMC * DIMC / 4;
        k_split<<<(n4 + 255) / 256, 256>>>(Wout, woh, wol, n4);
    }
    // 1) qkv via int8x3 tensor cores (Q pre-scaled by ATT_SCALE)
    k_qkv_i8<<<dim3(LDQKV / 128, (NB * NN) / 128), 512, I8_SMEM>>>();
    // 2) scores
    k_scores<<<dim3(NN / 128, NN / 128, NB * HEADS), 256, NT_SMEM>>>();
    // 3) mix + softmax + mix
    k_mix<<<NB * NN, 256, MIX_SMEM>>>(Lw, Lb, Ww, Wb);
    // 4) Av = A @ v
    k_av<<<dim3(1, NN / 128, NB * HEADS), 256, NN_SMEM>>>();
    // 5) O = (1-2λ)Av + 3λ A@Av
    k_aav<<<dim3(1, NN / 128, NB * HEADS), 256, NN_SMEM>>>(lamb);
    // 6) final projection
    k_out<<<dim3(DIMC / 128, (NB * NN) / 128), 256, NT_SMEM>>>(bout, out);
}